// round 1
// baseline (speedup 1.0000x reference)
#include <cuda_runtime.h>
#include <cuda_bf16.h>
#include <math.h>

// ---------------------------------------------------------------------------
// MLA forward, fp32 SIMT baseline.
// Shapes: B=1, S=2048, HID=2048, H=16, Q_LORA=1536, KV_LORA=512,
//         ROPE_D=64, NOPE_D=128, V_D=128, Q_HD=192.
// ---------------------------------------------------------------------------

#define S_LEN 2048
#define HID 2048
#define NH 16
#define Q_LORA 1536
#define KV_LORA 512
#define ROPE_D 64
#define NOPE_D 128
#define V_D 128
#define Q_HD 192       // NOPE_D + ROPE_D
#define KV_UPD 256     // NOPE_D + V_D

// ---------------- scratch (static device globals; no allocation) -----------
__device__ float g_qdown[S_LEN * Q_LORA];
__device__ float g_qn[S_LEN * Q_LORA];
__device__ float g_q[S_LEN * NH * Q_HD];       // 2048 x 3072
__device__ float g_c[S_LEN * (KV_LORA + ROPE_D)];   // 2048 x 576
__device__ float g_ckvn[S_LEN * KV_LORA];
__device__ float g_kv[S_LEN * NH * KV_UPD];    // 2048 x 4096
__device__ float g_qs[NH * S_LEN * Q_HD];      // [h][s][192]
__device__ float g_ks[NH * S_LEN * Q_HD];      // [h][s][192]
__device__ float g_vs[NH * S_LEN * V_D];       // [h][s][128]
__device__ float g_att[S_LEN * HID];           // [s][h*128+d]

// ---------------- generic tiled SGEMM: C[M,N] = A[M,K] @ B[K,N] ------------
// 64x64 tile, BK=16, 256 threads, 4x4 per thread with strided (tx+16j) cols.
__global__ void sgemm_kernel(const float* __restrict__ A,
                             const float* __restrict__ B,
                             float* __restrict__ C,
                             int M, int N, int K) {
    __shared__ float As[16 * 65];   // padded: As[c*65 + r]
    __shared__ float Bs[16 * 64];   // Bs[r*64 + c]
    int tid = threadIdx.x;
    int ty = tid >> 4, tx = tid & 15;
    int by = blockIdx.y, bx = blockIdx.x;

    float acc[4][4];
#pragma unroll
    for (int i = 0; i < 4; i++)
#pragma unroll
        for (int j = 0; j < 4; j++) acc[i][j] = 0.f;

    for (int k0 = 0; k0 < K; k0 += 16) {
#pragma unroll
        for (int i = tid; i < 1024; i += 256) {
            int r = i >> 4, c = i & 15;
            As[c * 65 + r] = A[(size_t)(by * 64 + r) * K + k0 + c];
        }
#pragma unroll
        for (int i = tid; i < 1024; i += 256) {
            int r = i >> 6, c = i & 63;
            Bs[r * 64 + c] = B[(size_t)(k0 + r) * N + bx * 64 + c];
        }
        __syncthreads();
#pragma unroll
        for (int kk = 0; kk < 16; kk++) {
            float a[4], b[4];
#pragma unroll
            for (int i = 0; i < 4; i++) a[i] = As[kk * 65 + ty + 16 * i];
#pragma unroll
            for (int j = 0; j < 4; j++) b[j] = Bs[kk * 64 + tx + 16 * j];
#pragma unroll
            for (int i = 0; i < 4; i++)
#pragma unroll
                for (int j = 0; j < 4; j++) acc[i][j] += a[i] * b[j];
        }
        __syncthreads();
    }
#pragma unroll
    for (int i = 0; i < 4; i++)
#pragma unroll
        for (int j = 0; j < 4; j++)
            C[(size_t)(by * 64 + ty + 16 * i) * N + bx * 64 + tx + 16 * j] = acc[i][j];
}

// ---------------- RMSNorm (one block per row) ------------------------------
__global__ void rmsnorm_kernel(const float* __restrict__ in,
                               const float* __restrict__ w,
                               float* __restrict__ out,
                               int width, int instride) {
    int row = blockIdx.x;
    const float* xr = in + (size_t)row * instride;
    float ss = 0.f;
    for (int i = threadIdx.x; i < width; i += 256) {
        float v = xr[i];
        ss += v * v;
    }
    __shared__ float red[256];
    red[threadIdx.x] = ss;
    __syncthreads();
#pragma unroll
    for (int s = 128; s > 0; s >>= 1) {
        if (threadIdx.x < s) red[threadIdx.x] += red[threadIdx.x + s];
        __syncthreads();
    }
    float scale = rsqrtf(red[0] / width + 1e-6f);
    for (int i = threadIdx.x; i < width; i += 256)
        out[(size_t)row * width + i] = xr[i] * scale * w[i];
}

// ---------------- RoPE + head-major repack ---------------------------------
// grid (S, H), 192 threads. Builds qs/ks [h][s][192], vs [h][s][128].
__global__ void rope_pack_kernel(const float* __restrict__ q,
                                 const float* __restrict__ kv,
                                 const float* __restrict__ c,
                                 const int* __restrict__ position,
                                 float* __restrict__ qs,
                                 float* __restrict__ ks,
                                 float* __restrict__ vs) {
    int s = blockIdx.x, h = blockIdx.y, d = threadIdx.x;
    float qv, kvv;
    if (d < NOPE_D) {
        qv = q[(size_t)s * (NH * Q_HD) + h * Q_HD + d];
        kvv = kv[(size_t)s * (NH * KV_UPD) + h * KV_UPD + d];
        vs[((size_t)h * S_LEN + s) * V_D + d] =
            kv[(size_t)s * (NH * KV_UPD) + h * KV_UPD + NOPE_D + d];
    } else {
        int dr = d - NOPE_D;           // [0,64)
        int i = dr & 31;
        double pos = (double)position[s];
        double invf = pow(10000.0, -((double)(2 * i)) / 64.0);
        double ang = pos * invf;
        float cv = (float)cos(ang);
        float sv = (float)sin(ang);
        const float* qr = q + (size_t)s * (NH * Q_HD) + h * Q_HD + NOPE_D;
        float xq = qr[dr];
        float rq = (dr < 32) ? -qr[dr + 32] : qr[dr - 32];
        qv = xq * cv + rq * sv;
        const float* kr = c + (size_t)s * (KV_LORA + ROPE_D) + KV_LORA;
        float xk = kr[dr];
        float rk = (dr < 32) ? -kr[dr + 32] : kr[dr - 32];
        kvv = xk * cv + rk * sv;
    }
    qs[((size_t)h * S_LEN + s) * Q_HD + d] = qv;
    ks[((size_t)h * S_LEN + s) * Q_HD + d] = kvv;
}

// ---------------- flash attention (causal), fp32 ---------------------------
// grid (S/64, H), 256 threads, 64-query tile, 64-key tiles.
#define KPAD 193   // 192 rows padded to break 192 % 32 == 0 bank alias
#define ATTN_SMEM_FLOATS (64 * Q_HD + 64 * KPAD + 64 * V_D + 64 * 64 + 192)

__global__ void attn_kernel(const float* __restrict__ qs,
                            const float* __restrict__ ks,
                            const float* __restrict__ vs,
                            float* __restrict__ att) {
    extern __shared__ float sm[];
    float* Qs = sm;                       // 64*192
    float* Ks = Qs + 64 * Q_HD;           // 64*193
    float* Vs = Ks + 64 * KPAD;           // 64*128
    float* Ss = Vs + 64 * V_D;            // 64*64
    float* mrow = Ss + 64 * 64;           // 64
    float* lrow = mrow + 64;              // 64
    float* frow = lrow + 64;              // 64

    int qt = blockIdx.x, h = blockIdx.y;
    int tid = threadIdx.x;
    int ty = tid >> 4, tx = tid & 15;

    const float* qh = qs + (size_t)h * S_LEN * Q_HD;
    const float* kh = ks + (size_t)h * S_LEN * Q_HD;
    const float* vh = vs + (size_t)h * S_LEN * V_D;

    for (int i = tid; i < 64 * Q_HD; i += 256) {
        int r = i / Q_HD, c = i % Q_HD;
        Qs[r * Q_HD + c] = qh[((size_t)qt * 64 + r) * Q_HD + c];
    }
    if (tid < 64) { mrow[tid] = -1e30f; lrow[tid] = 0.f; }

    float o[4][8];
#pragma unroll
    for (int i = 0; i < 4; i++)
#pragma unroll
        for (int j = 0; j < 8; j++) o[i][j] = 0.f;

    const float sc = 0.08838834764831845f;   // 1/sqrt(128)

    for (int kt = 0; kt <= qt; kt++) {
        __syncthreads();   // prior P@V done before overwriting Ks/Vs
        for (int i = tid; i < 64 * Q_HD; i += 256) {
            int r = i / Q_HD, c = i % Q_HD;
            Ks[r * KPAD + c] = kh[((size_t)kt * 64 + r) * Q_HD + c];
        }
        for (int i = tid; i < 64 * V_D; i += 256)
            Vs[i] = vh[(size_t)kt * 64 * V_D + i];
        __syncthreads();

        // S tile = Q @ K^T
        float acc[4][4];
#pragma unroll
        for (int i = 0; i < 4; i++)
#pragma unroll
            for (int j = 0; j < 4; j++) acc[i][j] = 0.f;
        for (int k = 0; k < Q_HD; k++) {
            float a[4], b[4];
#pragma unroll
            for (int i = 0; i < 4; i++) a[i] = Qs[(ty * 4 + i) * Q_HD + k];
#pragma unroll
            for (int j = 0; j < 4; j++) b[j] = Ks[(tx + 16 * j) * KPAD + k];
#pragma unroll
            for (int i = 0; i < 4; i++)
#pragma unroll
                for (int j = 0; j < 4; j++) acc[i][j] += a[i] * b[j];
        }
        bool diag = (kt == qt);
#pragma unroll
        for (int i = 0; i < 4; i++)
#pragma unroll
            for (int j = 0; j < 4; j++) {
                int r = ty * 4 + i, cc = tx + 16 * j;
                float v = acc[i][j] * sc;
                if (diag && cc > r) v = -1e30f;
                Ss[r * 64 + cc] = v;
            }
        __syncthreads();

        // online softmax per row (64 threads)
        if (tid < 64) {
            int r = tid;
            float mt = -1e30f;
            for (int c2 = 0; c2 < 64; c2++) mt = fmaxf(mt, Ss[r * 64 + c2]);
            float nm = fmaxf(mrow[r], mt);
            float f = __expf(mrow[r] - nm);
            float sum = 0.f;
            for (int c2 = 0; c2 < 64; c2++) {
                float p = __expf(Ss[r * 64 + c2] - nm);
                Ss[r * 64 + c2] = p;
                sum += p;
            }
            lrow[r] = lrow[r] * f + sum;
            frow[r] = f;
            mrow[r] = nm;
        }
        __syncthreads();

        // O = O*f + P @ V
#pragma unroll
        for (int i = 0; i < 4; i++) {
            float f = frow[ty * 4 + i];
#pragma unroll
            for (int j = 0; j < 8; j++) o[i][j] *= f;
        }
        for (int k = 0; k < 64; k++) {
            float p[4], v[8];
#pragma unroll
            for (int i = 0; i < 4; i++) p[i] = Ss[(ty * 4 + i) * 64 + k];
#pragma unroll
            for (int j = 0; j < 8; j++) v[j] = Vs[k * V_D + tx + 16 * j];
#pragma unroll
            for (int i = 0; i < 4; i++)
#pragma unroll
                for (int j = 0; j < 8; j++) o[i][j] += p[i] * v[j];
        }
    }

#pragma unroll
    for (int i = 0; i < 4; i++) {
        int r = ty * 4 + i;
        float inv = 1.f / lrow[r];
#pragma unroll
        for (int j = 0; j < 8; j++)
            att[((size_t)(qt * 64 + r)) * HID + h * V_D + tx + 16 * j] = o[i][j] * inv;
    }
}

// ---------------------------------------------------------------------------
extern "C" void kernel_launch(void* const* d_in, const int* in_sizes, int n_in,
                              void* d_out, int out_size) {
    const float* x        = (const float*)d_in[0];
    const int*   position = (const int*)d_in[1];
    // d_in[2] = mask (causal, hardcoded)
    const float* Wq_down  = (const float*)d_in[3];
    const float* q_norm_w = (const float*)d_in[4];
    const float* Wq_up    = (const float*)d_in[5];
    const float* Wkv_down = (const float*)d_in[6];
    const float* kv_norm_w= (const float*)d_in[7];
    const float* Wkv_up   = (const float*)d_in[8];
    const float* Wout     = (const float*)d_in[9];
    float* out = (float*)d_out;

    float *qdown, *qn, *q, *c, *ckvn, *kv, *qs, *ks, *vs, *att;
    cudaGetSymbolAddress((void**)&qdown, g_qdown);
    cudaGetSymbolAddress((void**)&qn, g_qn);
    cudaGetSymbolAddress((void**)&q, g_q);
    cudaGetSymbolAddress((void**)&c, g_c);
    cudaGetSymbolAddress((void**)&ckvn, g_ckvn);
    cudaGetSymbolAddress((void**)&kv, g_kv);
    cudaGetSymbolAddress((void**)&qs, g_qs);
    cudaGetSymbolAddress((void**)&ks, g_ks);
    cudaGetSymbolAddress((void**)&vs, g_vs);
    cudaGetSymbolAddress((void**)&att, g_att);

    dim3 blk(256);

    // q path
    sgemm_kernel<<<dim3(Q_LORA / 64, S_LEN / 64), blk>>>(x, Wq_down, qdown, S_LEN, Q_LORA, HID);
    rmsnorm_kernel<<<S_LEN, 256>>>(qdown, q_norm_w, qn, Q_LORA, Q_LORA);
    sgemm_kernel<<<dim3((NH * Q_HD) / 64, S_LEN / 64), blk>>>(qn, Wq_up, q, S_LEN, NH * Q_HD, Q_LORA);

    // kv path
    sgemm_kernel<<<dim3((KV_LORA + ROPE_D) / 64, S_LEN / 64), blk>>>(x, Wkv_down, c, S_LEN, KV_LORA + ROPE_D, HID);
    rmsnorm_kernel<<<S_LEN, 256>>>(c, kv_norm_w, ckvn, KV_LORA, KV_LORA + ROPE_D);
    sgemm_kernel<<<dim3((NH * KV_UPD) / 64, S_LEN / 64), blk>>>(ckvn, Wkv_up, kv, S_LEN, NH * KV_UPD, KV_LORA);

    // rope + repack
    rope_pack_kernel<<<dim3(S_LEN, NH), Q_HD>>>(q, kv, c, position, qs, ks, vs);

    // attention
    size_t smem = ATTN_SMEM_FLOATS * sizeof(float);
    cudaFuncSetAttribute(attn_kernel, cudaFuncAttributeMaxDynamicSharedMemorySize, (int)smem);
    attn_kernel<<<dim3(S_LEN / 64, NH), blk, smem>>>(qs, ks, vs, att);

    // output projection
    sgemm_kernel<<<dim3(HID / 64, S_LEN / 64), blk>>>(att, Wout, out, S_LEN, HID, HID);
}

// round 2
// speedup vs baseline: 1.6503x; 1.6503x over previous
#include <cuda_runtime.h>
#include <cuda_bf16.h>
#include <math.h>

// ---------------------------------------------------------------------------
// MLA forward, fp32 SIMT, round 2: 128x128 double-buffered SGEMM + vectorized
// flash attention.
// Shapes: B=1, S=2048, HID=2048, H=16, Q_LORA=1536, KV_LORA=512,
//         ROPE_D=64, NOPE_D=128, V_D=128, Q_HD=192.
// ---------------------------------------------------------------------------

#define S_LEN 2048
#define HID 2048
#define NH 16
#define Q_LORA 1536
#define KV_LORA 512
#define ROPE_D 64
#define NOPE_D 128
#define V_D 128
#define Q_HD 192       // NOPE_D + ROPE_D
#define KV_UPD 256     // NOPE_D + V_D

// ---------------- scratch (static device globals; no allocation) -----------
__device__ float g_qdown[S_LEN * Q_LORA];
__device__ float g_qn[S_LEN * Q_LORA];
__device__ float g_q[S_LEN * NH * Q_HD];
__device__ float g_c[S_LEN * (KV_LORA + ROPE_D)];
__device__ float g_ckvn[S_LEN * KV_LORA];
__device__ float g_kv[S_LEN * NH * KV_UPD];
__device__ float g_qs[NH * S_LEN * Q_HD];
__device__ float g_ks[NH * S_LEN * Q_HD];
__device__ float g_vs[NH * S_LEN * V_D];
__device__ float g_att[S_LEN * HID];
__device__ float g_rope[S_LEN * 64];   // [s][cos32 | sin32]

// ---------------- SGEMM: C[M,N] = A[M,K] @ B[K,N] --------------------------
// Tile BM=(64*RI) x 128, BK=16, 256 threads, (RI*4)x8 per thread.
// Double-buffered smem, float4 global loads, N-edge guarded.
template <int RI>
__global__ void __launch_bounds__(256, 2)
sgemm_t(const float* __restrict__ A, const float* __restrict__ B,
        float* __restrict__ C, int M, int N, int K) {
    constexpr int BM = 64 * RI;
    constexpr int AP = BM + 4;
    __shared__ float As[2][16][AP];
    __shared__ float Bs[2][16][128];

    int tid = threadIdx.x;
    int tx = tid & 15, ty = tid >> 4;
    int row0 = blockIdx.y * BM;
    int col0 = blockIdx.x * 128;

    int ar = tid >> 2, ac = (tid & 3) * 4;      // A: row ar(+64), cols ac..ac+3
    int bn = (tid & 31) * 4, br = tid >> 5;     // B: row br(+8), cols bn..bn+3
    bool bvalid = (col0 + bn) < N;

    float4 rA[RI], rB[2];
    float acc[RI * 4][8];
#pragma unroll
    for (int i = 0; i < RI * 4; i++)
#pragma unroll
        for (int j = 0; j < 8; j++) acc[i][j] = 0.f;

    const int nt = K / 16;

    // prologue: load tile 0
    {
#pragma unroll
        for (int i = 0; i < RI; i++)
            rA[i] = *(const float4*)&A[(size_t)(row0 + ar + 64 * i) * K + ac];
#pragma unroll
        for (int i = 0; i < 2; i++)
            rB[i] = bvalid ? *(const float4*)&B[(size_t)(br + 8 * i) * N + col0 + bn]
                           : make_float4(0.f, 0.f, 0.f, 0.f);
#pragma unroll
        for (int i = 0; i < RI; i++) {
            As[0][ac + 0][ar + 64 * i] = rA[i].x;
            As[0][ac + 1][ar + 64 * i] = rA[i].y;
            As[0][ac + 2][ar + 64 * i] = rA[i].z;
            As[0][ac + 3][ar + 64 * i] = rA[i].w;
        }
#pragma unroll
        for (int i = 0; i < 2; i++)
            *(float4*)&Bs[0][br + 8 * i][bn] = rB[i];
    }
    __syncthreads();

    int buf = 0;
    for (int t = 0; t < nt; t++) {
        if (t + 1 < nt) {
            int k0 = (t + 1) * 16;
#pragma unroll
            for (int i = 0; i < RI; i++)
                rA[i] = *(const float4*)&A[(size_t)(row0 + ar + 64 * i) * K + k0 + ac];
#pragma unroll
            for (int i = 0; i < 2; i++)
                rB[i] = bvalid ? *(const float4*)&B[(size_t)(k0 + br + 8 * i) * N + col0 + bn]
                               : make_float4(0.f, 0.f, 0.f, 0.f);
        }
#pragma unroll
        for (int kk = 0; kk < 16; kk++) {
            float a[RI * 4], b[8];
#pragma unroll
            for (int i = 0; i < RI; i++) {
                float4 av = *(float4*)&As[buf][kk][64 * i + ty * 4];
                a[i * 4 + 0] = av.x; a[i * 4 + 1] = av.y;
                a[i * 4 + 2] = av.z; a[i * 4 + 3] = av.w;
            }
            float4 b0 = *(float4*)&Bs[buf][kk][tx * 4];
            float4 b1 = *(float4*)&Bs[buf][kk][64 + tx * 4];
            b[0] = b0.x; b[1] = b0.y; b[2] = b0.z; b[3] = b0.w;
            b[4] = b1.x; b[5] = b1.y; b[6] = b1.z; b[7] = b1.w;
#pragma unroll
            for (int i = 0; i < RI * 4; i++)
#pragma unroll
                for (int j = 0; j < 8; j++) acc[i][j] += a[i] * b[j];
        }
        if (t + 1 < nt) {
            int nb = buf ^ 1;
#pragma unroll
            for (int i = 0; i < RI; i++) {
                As[nb][ac + 0][ar + 64 * i] = rA[i].x;
                As[nb][ac + 1][ar + 64 * i] = rA[i].y;
                As[nb][ac + 2][ar + 64 * i] = rA[i].z;
                As[nb][ac + 3][ar + 64 * i] = rA[i].w;
            }
#pragma unroll
            for (int i = 0; i < 2; i++)
                *(float4*)&Bs[nb][br + 8 * i][bn] = rB[i];
            __syncthreads();
            buf = nb;
        }
    }

#pragma unroll
    for (int i = 0; i < RI; i++)
#pragma unroll
        for (int u = 0; u < 4; u++) {
            size_t r = row0 + 64 * i + ty * 4 + u;
#pragma unroll
            for (int jj = 0; jj < 2; jj++) {
                int cb = col0 + 64 * jj + tx * 4;
                if (cb < N) {
                    float4 v;
                    v.x = acc[i * 4 + u][jj * 4 + 0];
                    v.y = acc[i * 4 + u][jj * 4 + 1];
                    v.z = acc[i * 4 + u][jj * 4 + 2];
                    v.w = acc[i * 4 + u][jj * 4 + 3];
                    *(float4*)&C[r * N + cb] = v;
                }
            }
        }
}

// ---------------- RMSNorm (one block per row) ------------------------------
__global__ void rmsnorm_kernel(const float* __restrict__ in,
                               const float* __restrict__ w,
                               float* __restrict__ out,
                               int width, int instride) {
    int row = blockIdx.x;
    const float* xr = in + (size_t)row * instride;
    float ss = 0.f;
    for (int i = threadIdx.x; i < width; i += 256) {
        float v = xr[i];
        ss += v * v;
    }
    __shared__ float red[256];
    red[threadIdx.x] = ss;
    __syncthreads();
#pragma unroll
    for (int s = 128; s > 0; s >>= 1) {
        if (threadIdx.x < s) red[threadIdx.x] += red[threadIdx.x + s];
        __syncthreads();
    }
    float scale = rsqrtf(red[0] / width + 1e-6f);
    for (int i = threadIdx.x; i < width; i += 256)
        out[(size_t)row * width + i] = xr[i] * scale * w[i];
}

// ---------------- RoPE table (fp64 angles, computed once) ------------------
__global__ void rope_table_kernel(const int* __restrict__ position) {
    int s = blockIdx.x, i = threadIdx.x;   // i in [0,32)
    double pos = (double)position[s];
    double invf = pow(10000.0, -((double)(2 * i)) / 64.0);
    double ang = pos * invf;
    g_rope[s * 64 + i] = (float)cos(ang);
    g_rope[s * 64 + 32 + i] = (float)sin(ang);
}

// ---------------- RoPE + head-major repack ---------------------------------
__global__ void rope_pack_kernel(const float* __restrict__ q,
                                 const float* __restrict__ kv,
                                 const float* __restrict__ c,
                                 float* __restrict__ qs,
                                 float* __restrict__ ks,
                                 float* __restrict__ vs) {
    int s = blockIdx.x, h = blockIdx.y, d = threadIdx.x;
    float qv, kvv;
    if (d < NOPE_D) {
        qv = q[(size_t)s * (NH * Q_HD) + h * Q_HD + d];
        kvv = kv[(size_t)s * (NH * KV_UPD) + h * KV_UPD + d];
        vs[((size_t)h * S_LEN + s) * V_D + d] =
            kv[(size_t)s * (NH * KV_UPD) + h * KV_UPD + NOPE_D + d];
    } else {
        int dr = d - NOPE_D;
        int i = dr & 31;
        float cv = g_rope[s * 64 + i];
        float sv = g_rope[s * 64 + 32 + i];
        const float* qr = q + (size_t)s * (NH * Q_HD) + h * Q_HD + NOPE_D;
        float xq = qr[dr];
        float rq = (dr < 32) ? -qr[dr + 32] : qr[dr - 32];
        qv = xq * cv + rq * sv;
        const float* kr = c + (size_t)s * (KV_LORA + ROPE_D) + KV_LORA;
        float xk = kr[dr];
        float rk = (dr < 32) ? -kr[dr + 32] : kr[dr - 32];
        kvv = xk * cv + rk * sv;
    }
    qs[((size_t)h * S_LEN + s) * Q_HD + d] = qv;
    ks[((size_t)h * S_LEN + s) * Q_HD + d] = kvv;
}

// ---------------- flash attention (causal), fp32, vectorized ---------------
#define KPAD2 196  // 192 padded, float4-aligned
#define SPAD 66
#define ATTN_SMEM_FLOATS (64 * Q_HD + 64 * KPAD2 + 64 * V_D + 64 * SPAD + 192)

__global__ void attn_kernel(const float* __restrict__ qs,
                            const float* __restrict__ ks,
                            const float* __restrict__ vs,
                            float* __restrict__ att) {
    extern __shared__ float sm[];
    float* Qs = sm;                         // 64*192
    float* Ks = Qs + 64 * Q_HD;             // 64*196
    float* Vs = Ks + 64 * KPAD2;            // 64*128
    float* Ss = Vs + 64 * V_D;              // 64*66
    float* mrow = Ss + 64 * SPAD;           // 64
    float* lrow = mrow + 64;                // 64
    float* frow = lrow + 64;                // 64

    int qt = gridDim.x - 1 - blockIdx.x;    // longest blocks first
    int h = blockIdx.y;
    int tid = threadIdx.x;
    int ty = tid >> 4, tx = tid & 15;

    const float* qh = qs + (size_t)h * S_LEN * Q_HD;
    const float* kh = ks + (size_t)h * S_LEN * Q_HD;
    const float* vh = vs + (size_t)h * S_LEN * V_D;

    // Q tile -> smem (float4)
#pragma unroll
    for (int idx = tid; idx < 64 * 48; idx += 256) {
        int r = idx / 48, c4 = idx % 48;
        *(float4*)&Qs[r * Q_HD + c4 * 4] =
            *(const float4*)&qh[((size_t)qt * 64 + r) * Q_HD + c4 * 4];
    }
    if (tid < 64) { mrow[tid] = -1e30f; lrow[tid] = 0.f; }

    float o[4][8];
#pragma unroll
    for (int i = 0; i < 4; i++)
#pragma unroll
        for (int j = 0; j < 8; j++) o[i][j] = 0.f;

    const float sc = 0.08838834764831845f;   // 1/sqrt(128)
    int rr = tid >> 2, rq = tid & 3;         // softmax mapping

    for (int kt = 0; kt <= qt; kt++) {
        __syncthreads();
#pragma unroll
        for (int idx = tid; idx < 64 * 48; idx += 256) {
            int r = idx / 48, c4 = idx % 48;
            *(float4*)&Ks[r * KPAD2 + c4 * 4] =
                *(const float4*)&kh[((size_t)kt * 64 + r) * Q_HD + c4 * 4];
        }
#pragma unroll
        for (int idx = tid; idx < 64 * 32; idx += 256)
            *(float4*)&Vs[idx * 4] = *(const float4*)&vh[(size_t)kt * 64 * V_D + idx * 4];
        __syncthreads();

        // S = Q @ K^T (k-vectorized)
        float acc[4][4];
#pragma unroll
        for (int i = 0; i < 4; i++)
#pragma unroll
            for (int j = 0; j < 4; j++) acc[i][j] = 0.f;
        for (int k = 0; k < Q_HD; k += 4) {
            float4 a4[4], b4[4];
#pragma unroll
            for (int i = 0; i < 4; i++) a4[i] = *(float4*)&Qs[(ty * 4 + i) * Q_HD + k];
#pragma unroll
            for (int j = 0; j < 4; j++) b4[j] = *(float4*)&Ks[(tx + 16 * j) * KPAD2 + k];
#pragma unroll
            for (int i = 0; i < 4; i++)
#pragma unroll
                for (int j = 0; j < 4; j++) {
                    acc[i][j] += a4[i].x * b4[j].x;
                    acc[i][j] += a4[i].y * b4[j].y;
                    acc[i][j] += a4[i].z * b4[j].z;
                    acc[i][j] += a4[i].w * b4[j].w;
                }
        }
        bool diag = (kt == qt);
#pragma unroll
        for (int i = 0; i < 4; i++)
#pragma unroll
            for (int j = 0; j < 4; j++) {
                int r = ty * 4 + i, cc = tx + 16 * j;
                float v = acc[i][j] * sc;
                if (diag && cc > r) v = -1e30f;
                Ss[r * SPAD + cc] = v;
            }
        __syncthreads();

        // online softmax, 4 threads per row
        {
            float mold = mrow[rr];
            float mt = -1e30f;
#pragma unroll
            for (int c2 = rq * 16; c2 < rq * 16 + 16; c2++)
                mt = fmaxf(mt, Ss[rr * SPAD + c2]);
            mt = fmaxf(mt, __shfl_xor_sync(0xFFFFFFFFu, mt, 1, 4));
            mt = fmaxf(mt, __shfl_xor_sync(0xFFFFFFFFu, mt, 2, 4));
            float nm = fmaxf(mold, mt);
            float sum = 0.f;
#pragma unroll
            for (int c2 = rq * 16; c2 < rq * 16 + 16; c2++) {
                float p = __expf(Ss[rr * SPAD + c2] - nm);
                Ss[rr * SPAD + c2] = p;
                sum += p;
            }
            sum += __shfl_xor_sync(0xFFFFFFFFu, sum, 1, 4);
            sum += __shfl_xor_sync(0xFFFFFFFFu, sum, 2, 4);
            __syncwarp();
            if (rq == 0) {
                float f = __expf(mold - nm);
                lrow[rr] = lrow[rr] * f + sum;
                frow[rr] = f;
                mrow[rr] = nm;
            }
        }
        __syncthreads();

        // O = O*f + P @ V
#pragma unroll
        for (int i = 0; i < 4; i++) {
            float f = frow[ty * 4 + i];
#pragma unroll
            for (int j = 0; j < 8; j++) o[i][j] *= f;
        }
        for (int k = 0; k < 64; k++) {
            float p[4];
#pragma unroll
            for (int i = 0; i < 4; i++) p[i] = Ss[(ty * 4 + i) * SPAD + k];
            float4 v0 = *(float4*)&Vs[k * V_D + tx * 4];
            float4 v1 = *(float4*)&Vs[k * V_D + 64 + tx * 4];
#pragma unroll
            for (int i = 0; i < 4; i++) {
                o[i][0] += p[i] * v0.x; o[i][1] += p[i] * v0.y;
                o[i][2] += p[i] * v0.z; o[i][3] += p[i] * v0.w;
                o[i][4] += p[i] * v1.x; o[i][5] += p[i] * v1.y;
                o[i][6] += p[i] * v1.z; o[i][7] += p[i] * v1.w;
            }
        }
    }

#pragma unroll
    for (int i = 0; i < 4; i++) {
        int r = ty * 4 + i;
        float inv = 1.f / lrow[r];
        float4 w0, w1;
        w0.x = o[i][0] * inv; w0.y = o[i][1] * inv;
        w0.z = o[i][2] * inv; w0.w = o[i][3] * inv;
        w1.x = o[i][4] * inv; w1.y = o[i][5] * inv;
        w1.z = o[i][6] * inv; w1.w = o[i][7] * inv;
        size_t base = ((size_t)(qt * 64 + r)) * HID + h * V_D;
        *(float4*)&att[base + tx * 4] = w0;
        *(float4*)&att[base + 64 + tx * 4] = w1;
    }
}

// ---------------------------------------------------------------------------
extern "C" void kernel_launch(void* const* d_in, const int* in_sizes, int n_in,
                              void* d_out, int out_size) {
    const float* x        = (const float*)d_in[0];
    const int*   position = (const int*)d_in[1];
    // d_in[2] = mask (causal, hardcoded)
    const float* Wq_down  = (const float*)d_in[3];
    const float* q_norm_w = (const float*)d_in[4];
    const float* Wq_up    = (const float*)d_in[5];
    const float* Wkv_down = (const float*)d_in[6];
    const float* kv_norm_w= (const float*)d_in[7];
    const float* Wkv_up   = (const float*)d_in[8];
    const float* Wout     = (const float*)d_in[9];
    float* out = (float*)d_out;

    float *qdown, *qn, *q, *c, *ckvn, *kv, *qs, *ks, *vs, *att;
    cudaGetSymbolAddress((void**)&qdown, g_qdown);
    cudaGetSymbolAddress((void**)&qn, g_qn);
    cudaGetSymbolAddress((void**)&q, g_q);
    cudaGetSymbolAddress((void**)&c, g_c);
    cudaGetSymbolAddress((void**)&ckvn, g_ckvn);
    cudaGetSymbolAddress((void**)&kv, g_kv);
    cudaGetSymbolAddress((void**)&qs, g_qs);
    cudaGetSymbolAddress((void**)&ks, g_ks);
    cudaGetSymbolAddress((void**)&vs, g_vs);
    cudaGetSymbolAddress((void**)&att, g_att);

    dim3 blk(256);

    // rope table (independent of q/kv paths)
    rope_table_kernel<<<S_LEN, 32>>>(position);

    // q path
    sgemm_t<2><<<dim3(Q_LORA / 128, S_LEN / 128), blk>>>(x, Wq_down, qdown, S_LEN, Q_LORA, HID);
    rmsnorm_kernel<<<S_LEN, 256>>>(qdown, q_norm_w, qn, Q_LORA, Q_LORA);
    sgemm_t<2><<<dim3((NH * Q_HD) / 128, S_LEN / 128), blk>>>(qn, Wq_up, q, S_LEN, NH * Q_HD, Q_LORA);

    // kv path (N=576 -> 64-row tiles, 5 col tiles with guard)
    sgemm_t<1><<<dim3(5, S_LEN / 64), blk>>>(x, Wkv_down, c, S_LEN, KV_LORA + ROPE_D, HID);
    rmsnorm_kernel<<<S_LEN, 256>>>(c, kv_norm_w, ckvn, KV_LORA, KV_LORA + ROPE_D);
    sgemm_t<2><<<dim3((NH * KV_UPD) / 128, S_LEN / 128), blk>>>(ckvn, Wkv_up, kv, S_LEN, NH * KV_UPD, KV_LORA);

    // rope + repack
    rope_pack_kernel<<<dim3(S_LEN, NH), Q_HD>>>(q, kv, c, qs, ks, vs);

    // attention
    size_t smem = ATTN_SMEM_FLOATS * sizeof(float);
    cudaFuncSetAttribute(attn_kernel, cudaFuncAttributeMaxDynamicSharedMemorySize, (int)smem);
    attn_kernel<<<dim3(S_LEN / 64, NH), blk, smem>>>(qs, ks, vs, att);

    // output projection
    sgemm_t<2><<<dim3(HID / 128, S_LEN / 128), blk>>>(att, Wout, out, S_LEN, HID, HID);
}

// round 3
// speedup vs baseline: 2.5557x; 1.5487x over previous
#include <cuda_runtime.h>
#include <cuda_bf16.h>
#include <math.h>
#include <stdint.h>

typedef __nv_bfloat16 bf16;

// ---------------------------------------------------------------------------
// MLA forward. Round 3: GEMMs via bf16x3 split-precision tensor-core mma.sync.
// Shapes: B=1, S=2048, HID=2048, H=16, Q_LORA=1536, KV_LORA=512,
//         ROPE_D=64, NOPE_D=128, V_D=128, Q_HD=192.
// ---------------------------------------------------------------------------

#define S_LEN 2048
#define HID 2048
#define NH 16
#define Q_LORA 1536
#define KV_LORA 512
#define ROPE_D 64
#define NOPE_D 128
#define V_D 128
#define Q_HD 192
#define KV_UPD 256

// ---------------- scratch (static device globals; no allocation) -----------
__device__ float g_qdown[S_LEN * Q_LORA];
__device__ float g_q[S_LEN * NH * Q_HD];
__device__ float g_c[S_LEN * (KV_LORA + ROPE_D)];
__device__ float g_kv[S_LEN * NH * KV_UPD];
__device__ float g_qs[NH * S_LEN * Q_HD];
__device__ float g_ks[NH * S_LEN * Q_HD];
__device__ float g_vs[NH * S_LEN * V_D];
__device__ float g_rope[S_LEN * 64];

// bf16 split pairs
__device__ bf16 g_xh[S_LEN * HID],               g_xl[S_LEN * HID];
__device__ bf16 g_wqdh[HID * Q_LORA],            g_wqdl[HID * Q_LORA];
__device__ bf16 g_wquh[Q_LORA * NH * Q_HD],      g_wqul[Q_LORA * NH * Q_HD];
__device__ bf16 g_wkdh[HID * (KV_LORA + ROPE_D)], g_wkdl[HID * (KV_LORA + ROPE_D)];
__device__ bf16 g_wkuh[KV_LORA * NH * KV_UPD],   g_wkul[KV_LORA * NH * KV_UPD];
__device__ bf16 g_woh[HID * HID],                g_wol[HID * HID];
__device__ bf16 g_qnh[S_LEN * Q_LORA],           g_qnl[S_LEN * Q_LORA];
__device__ bf16 g_cnh[S_LEN * KV_LORA],          g_cnl[S_LEN * KV_LORA];
__device__ bf16 g_atth[S_LEN * HID],             g_attl[S_LEN * HID];

// ---------------- helpers --------------------------------------------------
__device__ __forceinline__ uint32_t pk2(bf16 a, bf16 b) {
    return (uint32_t)__bfloat16_as_ushort(a) |
           ((uint32_t)__bfloat16_as_ushort(b) << 16);
}

__device__ __forceinline__ void mma16816(float* c, const uint32_t* a, const uint32_t* b) {
    asm volatile(
        "mma.sync.aligned.m16n8k16.row.col.f32.bf16.bf16.f32 "
        "{%0,%1,%2,%3}, {%4,%5,%6,%7}, {%8,%9}, {%0,%1,%2,%3};\n"
        : "+f"(c[0]), "+f"(c[1]), "+f"(c[2]), "+f"(c[3])
        : "r"(a[0]), "r"(a[1]), "r"(a[2]), "r"(a[3]), "r"(b[0]), "r"(b[1]));
}

// ---------------- fp32 -> (bf16 hi, bf16 lo) split -------------------------
__global__ void split_kernel(const float* __restrict__ x,
                             bf16* __restrict__ h, bf16* __restrict__ l) {
    size_t i = ((size_t)blockIdx.x * 256 + threadIdx.x) * 4;
    float4 v = *(const float4*)&x[i];
    bf16 h0 = __float2bfloat16(v.x), h1 = __float2bfloat16(v.y);
    bf16 h2 = __float2bfloat16(v.z), h3 = __float2bfloat16(v.w);
    bf16 l0 = __float2bfloat16(v.x - __bfloat162float(h0));
    bf16 l1 = __float2bfloat16(v.y - __bfloat162float(h1));
    bf16 l2 = __float2bfloat16(v.z - __bfloat162float(h2));
    bf16 l3 = __float2bfloat16(v.w - __bfloat162float(h3));
    *(uint2*)&h[i] = make_uint2(pk2(h0, h1), pk2(h2, h3));
    *(uint2*)&l[i] = make_uint2(pk2(l0, l1), pk2(l2, l3));
}

// ---------------- bf16x3 GEMM: C[M,N] = (Ah+Al)(Bh+Bl) ---------------------
// 128x128 tile, BK=32, 256 threads (8 warps as 2Mx4N, 64x32 warp tile).
// Double-buffered smem. A smem [m][k] pad 40; B smem [k][n] pad 136.
#define BKP 40
#define BNP 136
#define SMEM_GEMM ((2*128*BKP*2 + 2*32*BNP*2) * 2 * (int)sizeof(bf16) / 2)
// = 2 bufs * (Ah+Al: 128*40 each, Bh+Bl: 32*136 each) * 2B = 75776 bytes
#define SMEM_GEMM_BYTES (2 * (2 * 128 * BKP + 2 * 32 * BNP) * (int)sizeof(bf16))

__global__ void __launch_bounds__(256, 1)
hgemm3_kernel(const bf16* __restrict__ Ah, const bf16* __restrict__ Al,
              const bf16* __restrict__ Bh, const bf16* __restrict__ Bl,
              float* __restrict__ C, int M, int N, int K) {
    extern __shared__ bf16 sm_[];
    bf16* sAh = sm_;                     // [2][128*BKP]
    bf16* sAl = sAh + 2 * 128 * BKP;
    bf16* sBh = sAl + 2 * 128 * BKP;     // [2][32*BNP]
    bf16* sBl = sBh + 2 * 32 * BNP;

    const int tid = threadIdx.x;
    const int lane = tid & 31, wid = tid >> 5;
    const int g = lane >> 2, tg = lane & 3;
    const int warp_m = wid >> 2, warp_n = wid & 3;
    const int row0 = blockIdx.y * 128, col0 = blockIdx.x * 128;

    const int ar0 = tid >> 2, akc = tid & 3;   // A chunk: rows ar0, ar0+64
    const int bk0 = tid >> 4, bnch = tid & 15; // B chunk: k rows bk0, bk0+16
    const int colb = col0 + bnch * 8;
    const bool bv = colb < N;

    float acc[16][4];
#pragma unroll
    for (int i = 0; i < 16; i++)
#pragma unroll
        for (int j = 0; j < 4; j++) acc[i][j] = 0.f;

    uint4 rAh[2], rAl[2], rBh[2], rBl[2];
    const uint4 zz = make_uint4(0, 0, 0, 0);
    const int nt = K / 32;

    // prologue: load tile 0
    {
        size_t a0 = (size_t)(row0 + ar0) * K + akc * 8;
        size_t a1 = (size_t)(row0 + ar0 + 64) * K + akc * 8;
        rAh[0] = *(const uint4*)(Ah + a0); rAh[1] = *(const uint4*)(Ah + a1);
        rAl[0] = *(const uint4*)(Al + a0); rAl[1] = *(const uint4*)(Al + a1);
        size_t b0 = (size_t)bk0 * N + colb;
        size_t b1 = (size_t)(bk0 + 16) * N + colb;
        rBh[0] = bv ? *(const uint4*)(Bh + b0) : zz;
        rBh[1] = bv ? *(const uint4*)(Bh + b1) : zz;
        rBl[0] = bv ? *(const uint4*)(Bl + b0) : zz;
        rBl[1] = bv ? *(const uint4*)(Bl + b1) : zz;
    }
    {
        bf16* dAh = sAh; bf16* dAl = sAl; bf16* dBh = sBh; bf16* dBl = sBl;
        *(uint4*)(dAh + ar0 * BKP + akc * 8) = rAh[0];
        *(uint4*)(dAh + (ar0 + 64) * BKP + akc * 8) = rAh[1];
        *(uint4*)(dAl + ar0 * BKP + akc * 8) = rAl[0];
        *(uint4*)(dAl + (ar0 + 64) * BKP + akc * 8) = rAl[1];
        *(uint4*)(dBh + bk0 * BNP + bnch * 8) = rBh[0];
        *(uint4*)(dBh + (bk0 + 16) * BNP + bnch * 8) = rBh[1];
        *(uint4*)(dBl + bk0 * BNP + bnch * 8) = rBl[0];
        *(uint4*)(dBl + (bk0 + 16) * BNP + bnch * 8) = rBl[1];
    }
    __syncthreads();

    int buf = 0;
    for (int t = 0; t < nt; t++) {
        if (t + 1 < nt) {
            int k0 = (t + 1) * 32;
            size_t a0 = (size_t)(row0 + ar0) * K + k0 + akc * 8;
            size_t a1 = (size_t)(row0 + ar0 + 64) * K + k0 + akc * 8;
            rAh[0] = *(const uint4*)(Ah + a0); rAh[1] = *(const uint4*)(Ah + a1);
            rAl[0] = *(const uint4*)(Al + a0); rAl[1] = *(const uint4*)(Al + a1);
            size_t b0 = (size_t)(k0 + bk0) * N + colb;
            size_t b1 = (size_t)(k0 + bk0 + 16) * N + colb;
            rBh[0] = bv ? *(const uint4*)(Bh + b0) : zz;
            rBh[1] = bv ? *(const uint4*)(Bh + b1) : zz;
            rBl[0] = bv ? *(const uint4*)(Bl + b0) : zz;
            rBl[1] = bv ? *(const uint4*)(Bl + b1) : zz;
        }

        const bf16* cAh = sAh + buf * 128 * BKP;
        const bf16* cAl = sAl + buf * 128 * BKP;
        const bf16* cBh = sBh + buf * 32 * BNP;
        const bf16* cBl = sBl + buf * 32 * BNP;

#pragma unroll
        for (int kk = 0; kk < 2; kk++) {
            uint32_t fAh[4][4], fAl[4][4], fBh[4][2], fBl[4][2];
#pragma unroll
            for (int mf = 0; mf < 4; mf++) {
                const bf16* p = cAh + (warp_m * 64 + mf * 16 + g) * BKP + kk * 16 + tg * 2;
                fAh[mf][0] = *(const uint32_t*)p;
                fAh[mf][1] = *(const uint32_t*)(p + 8 * BKP);
                fAh[mf][2] = *(const uint32_t*)(p + 8);
                fAh[mf][3] = *(const uint32_t*)(p + 8 * BKP + 8);
                const bf16* q = cAl + (warp_m * 64 + mf * 16 + g) * BKP + kk * 16 + tg * 2;
                fAl[mf][0] = *(const uint32_t*)q;
                fAl[mf][1] = *(const uint32_t*)(q + 8 * BKP);
                fAl[mf][2] = *(const uint32_t*)(q + 8);
                fAl[mf][3] = *(const uint32_t*)(q + 8 * BKP + 8);
            }
#pragma unroll
            for (int nf = 0; nf < 4; nf++) {
                const bf16* p = cBh + (kk * 16 + tg * 2) * BNP + warp_n * 32 + nf * 8 + g;
                fBh[nf][0] = pk2(p[0], p[BNP]);
                fBh[nf][1] = pk2(p[8 * BNP], p[9 * BNP]);
                const bf16* q = cBl + (kk * 16 + tg * 2) * BNP + warp_n * 32 + nf * 8 + g;
                fBl[nf][0] = pk2(q[0], q[BNP]);
                fBl[nf][1] = pk2(q[8 * BNP], q[9 * BNP]);
            }
#pragma unroll
            for (int mf = 0; mf < 4; mf++)
#pragma unroll
                for (int nf = 0; nf < 4; nf++) {
                    float* c = acc[mf * 4 + nf];
                    mma16816(c, fAh[mf], fBh[nf]);
                    mma16816(c, fAh[mf], fBl[nf]);
                    mma16816(c, fAl[mf], fBh[nf]);
                }
        }

        if (t + 1 < nt) {
            int nb = buf ^ 1;
            bf16* dAh = sAh + nb * 128 * BKP;
            bf16* dAl = sAl + nb * 128 * BKP;
            bf16* dBh = sBh + nb * 32 * BNP;
            bf16* dBl = sBl + nb * 32 * BNP;
            *(uint4*)(dAh + ar0 * BKP + akc * 8) = rAh[0];
            *(uint4*)(dAh + (ar0 + 64) * BKP + akc * 8) = rAh[1];
            *(uint4*)(dAl + ar0 * BKP + akc * 8) = rAl[0];
            *(uint4*)(dAl + (ar0 + 64) * BKP + akc * 8) = rAl[1];
            *(uint4*)(dBh + bk0 * BNP + bnch * 8) = rBh[0];
            *(uint4*)(dBh + (bk0 + 16) * BNP + bnch * 8) = rBh[1];
            *(uint4*)(dBl + bk0 * BNP + bnch * 8) = rBl[0];
            *(uint4*)(dBl + (bk0 + 16) * BNP + bnch * 8) = rBl[1];
            __syncthreads();
            buf = nb;
        }
    }

#pragma unroll
    for (int mf = 0; mf < 4; mf++)
#pragma unroll
        for (int nf = 0; nf < 4; nf++) {
            int r = row0 + warp_m * 64 + mf * 16 + g;
            int cc = col0 + warp_n * 32 + nf * 8 + tg * 2;
            if (cc < N) {
                float* a = acc[mf * 4 + nf];
                *(float2*)&C[(size_t)r * N + cc] = make_float2(a[0], a[1]);
                *(float2*)&C[(size_t)(r + 8) * N + cc] = make_float2(a[2], a[3]);
            }
        }
}

// ---------------- RMSNorm with fused bf16 split output ---------------------
__global__ void rmsnorm_split_kernel(const float* __restrict__ in,
                                     const float* __restrict__ w,
                                     bf16* __restrict__ oh, bf16* __restrict__ ol,
                                     int width, int instride) {
    int row = blockIdx.x;
    const float* xr = in + (size_t)row * instride;
    float ss = 0.f;
    for (int i = threadIdx.x; i < width; i += 256) {
        float v = xr[i];
        ss += v * v;
    }
    __shared__ float red[256];
    red[threadIdx.x] = ss;
    __syncthreads();
#pragma unroll
    for (int s = 128; s > 0; s >>= 1) {
        if (threadIdx.x < s) red[threadIdx.x] += red[threadIdx.x + s];
        __syncthreads();
    }
    float scale = rsqrtf(red[0] / width + 1e-6f);
    for (int i = threadIdx.x; i < width; i += 256) {
        float v = xr[i] * scale * w[i];
        bf16 hv = __float2bfloat16(v);
        oh[(size_t)row * width + i] = hv;
        ol[(size_t)row * width + i] = __float2bfloat16(v - __bfloat162float(hv));
    }
}

// ---------------- RoPE table (fp64 angles, computed once) ------------------
__global__ void rope_table_kernel(const int* __restrict__ position) {
    int s = blockIdx.x, i = threadIdx.x;
    double pos = (double)position[s];
    double invf = pow(10000.0, -((double)(2 * i)) / 64.0);
    double ang = pos * invf;
    g_rope[s * 64 + i] = (float)cos(ang);
    g_rope[s * 64 + 32 + i] = (float)sin(ang);
}

// ---------------- RoPE + head-major repack ---------------------------------
__global__ void rope_pack_kernel(const float* __restrict__ q,
                                 const float* __restrict__ kv,
                                 const float* __restrict__ c,
                                 float* __restrict__ qs,
                                 float* __restrict__ ks,
                                 float* __restrict__ vs) {
    int s = blockIdx.x, h = blockIdx.y, d = threadIdx.x;
    float qv, kvv;
    if (d < NOPE_D) {
        qv = q[(size_t)s * (NH * Q_HD) + h * Q_HD + d];
        kvv = kv[(size_t)s * (NH * KV_UPD) + h * KV_UPD + d];
        vs[((size_t)h * S_LEN + s) * V_D + d] =
            kv[(size_t)s * (NH * KV_UPD) + h * KV_UPD + NOPE_D + d];
    } else {
        int dr = d - NOPE_D;
        int i = dr & 31;
        float cv = g_rope[s * 64 + i];
        float sv = g_rope[s * 64 + 32 + i];
        const float* qr = q + (size_t)s * (NH * Q_HD) + h * Q_HD + NOPE_D;
        float xq = qr[dr];
        float rq = (dr < 32) ? -qr[dr + 32] : qr[dr - 32];
        qv = xq * cv + rq * sv;
        const float* kr = c + (size_t)s * (KV_LORA + ROPE_D) + KV_LORA;
        float xk = kr[dr];
        float rk = (dr < 32) ? -kr[dr + 32] : kr[dr - 32];
        kvv = xk * cv + rk * sv;
    }
    qs[((size_t)h * S_LEN + s) * Q_HD + d] = qv;
    ks[((size_t)h * S_LEN + s) * Q_HD + d] = kvv;
}

// ---------------- flash attention (causal), fp32, split-bf16 output --------
#define KPAD2 196
#define SPAD 66
#define ATTN_SMEM_FLOATS (64 * Q_HD + 64 * KPAD2 + 64 * V_D + 64 * SPAD + 192)

__global__ void attn_kernel(const float* __restrict__ qs,
                            const float* __restrict__ ks,
                            const float* __restrict__ vs,
                            bf16* __restrict__ att_h,
                            bf16* __restrict__ att_l) {
    extern __shared__ float sm[];
    float* Qs = sm;
    float* Ks = Qs + 64 * Q_HD;
    float* Vs = Ks + 64 * KPAD2;
    float* Ss = Vs + 64 * V_D;
    float* mrow = Ss + 64 * SPAD;
    float* lrow = mrow + 64;
    float* frow = lrow + 64;

    int qt = gridDim.x - 1 - blockIdx.x;
    int h = blockIdx.y;
    int tid = threadIdx.x;
    int ty = tid >> 4, tx = tid & 15;

    const float* qh = qs + (size_t)h * S_LEN * Q_HD;
    const float* kh = ks + (size_t)h * S_LEN * Q_HD;
    const float* vh = vs + (size_t)h * S_LEN * V_D;

#pragma unroll
    for (int idx = tid; idx < 64 * 48; idx += 256) {
        int r = idx / 48, c4 = idx % 48;
        *(float4*)&Qs[r * Q_HD + c4 * 4] =
            *(const float4*)&qh[((size_t)qt * 64 + r) * Q_HD + c4 * 4];
    }
    if (tid < 64) { mrow[tid] = -1e30f; lrow[tid] = 0.f; }

    float o[4][8];
#pragma unroll
    for (int i = 0; i < 4; i++)
#pragma unroll
        for (int j = 0; j < 8; j++) o[i][j] = 0.f;

    const float sc = 0.08838834764831845f;
    int rr = tid >> 2, rq = tid & 3;

    for (int kt = 0; kt <= qt; kt++) {
        __syncthreads();
#pragma unroll
        for (int idx = tid; idx < 64 * 48; idx += 256) {
            int r = idx / 48, c4 = idx % 48;
            *(float4*)&Ks[r * KPAD2 + c4 * 4] =
                *(const float4*)&kh[((size_t)kt * 64 + r) * Q_HD + c4 * 4];
        }
#pragma unroll
        for (int idx = tid; idx < 64 * 32; idx += 256)
            *(float4*)&Vs[idx * 4] = *(const float4*)&vh[(size_t)kt * 64 * V_D + idx * 4];
        __syncthreads();

        float acc[4][4];
#pragma unroll
        for (int i = 0; i < 4; i++)
#pragma unroll
            for (int j = 0; j < 4; j++) acc[i][j] = 0.f;
        for (int k = 0; k < Q_HD; k += 4) {
            float4 a4[4], b4[4];
#pragma unroll
            for (int i = 0; i < 4; i++) a4[i] = *(float4*)&Qs[(ty * 4 + i) * Q_HD + k];
#pragma unroll
            for (int j = 0; j < 4; j++) b4[j] = *(float4*)&Ks[(tx + 16 * j) * KPAD2 + k];
#pragma unroll
            for (int i = 0; i < 4; i++)
#pragma unroll
                for (int j = 0; j < 4; j++) {
                    acc[i][j] += a4[i].x * b4[j].x;
                    acc[i][j] += a4[i].y * b4[j].y;
                    acc[i][j] += a4[i].z * b4[j].z;
                    acc[i][j] += a4[i].w * b4[j].w;
                }
        }
        bool diag = (kt == qt);
#pragma unroll
        for (int i = 0; i < 4; i++)
#pragma unroll
            for (int j = 0; j < 4; j++) {
                int r = ty * 4 + i, cc = tx + 16 * j;
                float v = acc[i][j] * sc;
                if (diag && cc > r) v = -1e30f;
                Ss[r * SPAD + cc] = v;
            }
        __syncthreads();

        {
            float mold = mrow[rr];
            float mt = -1e30f;
#pragma unroll
            for (int c2 = rq * 16; c2 < rq * 16 + 16; c2++)
                mt = fmaxf(mt, Ss[rr * SPAD + c2]);
            mt = fmaxf(mt, __shfl_xor_sync(0xFFFFFFFFu, mt, 1, 4));
            mt = fmaxf(mt, __shfl_xor_sync(0xFFFFFFFFu, mt, 2, 4));
            float nm = fmaxf(mold, mt);
            float sum = 0.f;
#pragma unroll
            for (int c2 = rq * 16; c2 < rq * 16 + 16; c2++) {
                float p = __expf(Ss[rr * SPAD + c2] - nm);
                Ss[rr * SPAD + c2] = p;
                sum += p;
            }
            sum += __shfl_xor_sync(0xFFFFFFFFu, sum, 1, 4);
            sum += __shfl_xor_sync(0xFFFFFFFFu, sum, 2, 4);
            __syncwarp();
            if (rq == 0) {
                float f = __expf(mold - nm);
                lrow[rr] = lrow[rr] * f + sum;
                frow[rr] = f;
                mrow[rr] = nm;
            }
        }
        __syncthreads();

#pragma unroll
        for (int i = 0; i < 4; i++) {
            float f = frow[ty * 4 + i];
#pragma unroll
            for (int j = 0; j < 8; j++) o[i][j] *= f;
        }
        for (int k = 0; k < 64; k++) {
            float p[4];
#pragma unroll
            for (int i = 0; i < 4; i++) p[i] = Ss[(ty * 4 + i) * SPAD + k];
            float4 v0 = *(float4*)&Vs[k * V_D + tx * 4];
            float4 v1 = *(float4*)&Vs[k * V_D + 64 + tx * 4];
#pragma unroll
            for (int i = 0; i < 4; i++) {
                o[i][0] += p[i] * v0.x; o[i][1] += p[i] * v0.y;
                o[i][2] += p[i] * v0.z; o[i][3] += p[i] * v0.w;
                o[i][4] += p[i] * v1.x; o[i][5] += p[i] * v1.y;
                o[i][6] += p[i] * v1.z; o[i][7] += p[i] * v1.w;
            }
        }
    }

#pragma unroll
    for (int i = 0; i < 4; i++) {
        int r = ty * 4 + i;
        float inv = 1.f / lrow[r];
        size_t base = ((size_t)(qt * 64 + r)) * HID + h * V_D;
#pragma unroll
        for (int jj = 0; jj < 2; jj++) {
            float v0 = o[i][jj * 4 + 0] * inv;
            float v1 = o[i][jj * 4 + 1] * inv;
            float v2 = o[i][jj * 4 + 2] * inv;
            float v3 = o[i][jj * 4 + 3] * inv;
            bf16 h0 = __float2bfloat16(v0), h1 = __float2bfloat16(v1);
            bf16 h2 = __float2bfloat16(v2), h3 = __float2bfloat16(v3);
            bf16 l0 = __float2bfloat16(v0 - __bfloat162float(h0));
            bf16 l1 = __float2bfloat16(v1 - __bfloat162float(h1));
            bf16 l2 = __float2bfloat16(v2 - __bfloat162float(h2));
            bf16 l3 = __float2bfloat16(v3 - __bfloat162float(h3));
            *(uint2*)&att_h[base + jj * 64 + tx * 4] = make_uint2(pk2(h0, h1), pk2(h2, h3));
            *(uint2*)&att_l[base + jj * 64 + tx * 4] = make_uint2(pk2(l0, l1), pk2(l2, l3));
        }
    }
}

// ---------------------------------------------------------------------------
extern "C" void kernel_launch(void* const* d_in, const int* in_sizes, int n_in,
                              void* d_out, int out_size) {
    const float* x        = (const float*)d_in[0];
    const int*   position = (const int*)d_in[1];
    // d_in[2] = mask (causal, hardcoded)
    const float* Wq_down  = (const float*)d_in[3];
    const float* q_norm_w = (const float*)d_in[4];
    const float* Wq_up    = (const float*)d_in[5];
    const float* Wkv_down = (const float*)d_in[6];
    const float* kv_norm_w= (const float*)d_in[7];
    const float* Wkv_up   = (const float*)d_in[8];
    const float* Wout     = (const float*)d_in[9];
    float* out = (float*)d_out;

    float *qdown, *q, *c, *kv, *qs, *ks, *vs;
    bf16 *xh, *xl, *wqdh, *wqdl, *wquh, *wqul, *wkdh, *wkdl, *wkuh, *wkul;
    bf16 *woh, *wol, *qnh, *qnl, *cnh, *cnl, *atth, *attl;
    cudaGetSymbolAddress((void**)&qdown, g_qdown);
    cudaGetSymbolAddress((void**)&q, g_q);
    cudaGetSymbolAddress((void**)&c, g_c);
    cudaGetSymbolAddress((void**)&kv, g_kv);
    cudaGetSymbolAddress((void**)&qs, g_qs);
    cudaGetSymbolAddress((void**)&ks, g_ks);
    cudaGetSymbolAddress((void**)&vs, g_vs);
    cudaGetSymbolAddress((void**)&xh, g_xh);   cudaGetSymbolAddress((void**)&xl, g_xl);
    cudaGetSymbolAddress((void**)&wqdh, g_wqdh); cudaGetSymbolAddress((void**)&wqdl, g_wqdl);
    cudaGetSymbolAddress((void**)&wquh, g_wquh); cudaGetSymbolAddress((void**)&wqul, g_wqul);
    cudaGetSymbolAddress((void**)&wkdh, g_wkdh); cudaGetSymbolAddress((void**)&wkdl, g_wkdl);
    cudaGetSymbolAddress((void**)&wkuh, g_wkuh); cudaGetSymbolAddress((void**)&wkul, g_wkul);
    cudaGetSymbolAddress((void**)&woh, g_woh);   cudaGetSymbolAddress((void**)&wol, g_wol);
    cudaGetSymbolAddress((void**)&qnh, g_qnh);   cudaGetSymbolAddress((void**)&qnl, g_qnl);
    cudaGetSymbolAddress((void**)&cnh, g_cnh);   cudaGetSymbolAddress((void**)&cnl, g_cnl);
    cudaGetSymbolAddress((void**)&atth, g_atth); cudaGetSymbolAddress((void**)&attl, g_attl);

    // splits (inputs + weights)
    split_kernel<<<(S_LEN * HID) / 1024, 256>>>(x, xh, xl);
    split_kernel<<<(HID * Q_LORA) / 1024, 256>>>(Wq_down, wqdh, wqdl);
    split_kernel<<<(Q_LORA * NH * Q_HD) / 1024, 256>>>(Wq_up, wquh, wqul);
    split_kernel<<<(HID * (KV_LORA + ROPE_D)) / 1024, 256>>>(Wkv_down, wkdh, wkdl);
    split_kernel<<<(KV_LORA * NH * KV_UPD) / 1024, 256>>>(Wkv_up, wkuh, wkul);
    split_kernel<<<(HID * HID) / 1024, 256>>>(Wout, woh, wol);

    rope_table_kernel<<<S_LEN, 32>>>(position);

    cudaFuncSetAttribute(hgemm3_kernel, cudaFuncAttributeMaxDynamicSharedMemorySize,
                         SMEM_GEMM_BYTES);
    dim3 blk(256);

    // q path
    hgemm3_kernel<<<dim3(Q_LORA / 128, S_LEN / 128), blk, SMEM_GEMM_BYTES>>>(
        xh, xl, wqdh, wqdl, qdown, S_LEN, Q_LORA, HID);
    rmsnorm_split_kernel<<<S_LEN, 256>>>(qdown, q_norm_w, qnh, qnl, Q_LORA, Q_LORA);
    hgemm3_kernel<<<dim3((NH * Q_HD) / 128, S_LEN / 128), blk, SMEM_GEMM_BYTES>>>(
        qnh, qnl, wquh, wqul, q, S_LEN, NH * Q_HD, Q_LORA);

    // kv path (N=576 -> 5 col tiles with guard)
    hgemm3_kernel<<<dim3(5, S_LEN / 128), blk, SMEM_GEMM_BYTES>>>(
        xh, xl, wkdh, wkdl, c, S_LEN, KV_LORA + ROPE_D, HID);
    rmsnorm_split_kernel<<<S_LEN, 256>>>(c, kv_norm_w, cnh, cnl, KV_LORA, KV_LORA + ROPE_D);
    hgemm3_kernel<<<dim3((NH * KV_UPD) / 128, S_LEN / 128), blk, SMEM_GEMM_BYTES>>>(
        cnh, cnl, wkuh, wkul, kv, S_LEN, NH * KV_UPD, KV_LORA);

    // rope + repack
    rope_pack_kernel<<<dim3(S_LEN, NH), Q_HD>>>(q, kv, c, qs, ks, vs);

    // attention (fp32 SIMT, split-bf16 output)
    size_t smem = ATTN_SMEM_FLOATS * sizeof(float);
    cudaFuncSetAttribute(attn_kernel, cudaFuncAttributeMaxDynamicSharedMemorySize, (int)smem);
    attn_kernel<<<dim3(S_LEN / 64, NH), blk, smem>>>(qs, ks, vs, atth, attl);

    // output projection
    hgemm3_kernel<<<dim3(HID / 128, S_LEN / 128), blk, SMEM_GEMM_BYTES>>>(
        atth, attl, woh, wol, out, S_LEN, HID, HID);
}

// round 4
// speedup vs baseline: 2.5562x; 1.0002x over previous
#include <cuda_runtime.h>
#include <cuda_bf16.h>
#include <math.h>
#include <stdint.h>

typedef __nv_bfloat16 bf16;

// ---------------------------------------------------------------------------
// MLA forward. Round 3: GEMMs via bf16x3 split-precision tensor-core mma.sync.
// Shapes: B=1, S=2048, HID=2048, H=16, Q_LORA=1536, KV_LORA=512,
//         ROPE_D=64, NOPE_D=128, V_D=128, Q_HD=192.
// ---------------------------------------------------------------------------

#define S_LEN 2048
#define HID 2048
#define NH 16
#define Q_LORA 1536
#define KV_LORA 512
#define ROPE_D 64
#define NOPE_D 128
#define V_D 128
#define Q_HD 192
#define KV_UPD 256

// ---------------- scratch (static device globals; no allocation) -----------
__device__ float g_qdown[S_LEN * Q_LORA];
__device__ float g_q[S_LEN * NH * Q_HD];
__device__ float g_c[S_LEN * (KV_LORA + ROPE_D)];
__device__ float g_kv[S_LEN * NH * KV_UPD];
__device__ float g_qs[NH * S_LEN * Q_HD];
__device__ float g_ks[NH * S_LEN * Q_HD];
__device__ float g_vs[NH * S_LEN * V_D];
__device__ float g_rope[S_LEN * 64];

// bf16 split pairs
__device__ bf16 g_xh[S_LEN * HID],               g_xl[S_LEN * HID];
__device__ bf16 g_wqdh[HID * Q_LORA],            g_wqdl[HID * Q_LORA];
__device__ bf16 g_wquh[Q_LORA * NH * Q_HD],      g_wqul[Q_LORA * NH * Q_HD];
__device__ bf16 g_wkdh[HID * (KV_LORA + ROPE_D)], g_wkdl[HID * (KV_LORA + ROPE_D)];
__device__ bf16 g_wkuh[KV_LORA * NH * KV_UPD],   g_wkul[KV_LORA * NH * KV_UPD];
__device__ bf16 g_woh[HID * HID],                g_wol[HID * HID];
__device__ bf16 g_qnh[S_LEN * Q_LORA],           g_qnl[S_LEN * Q_LORA];
__device__ bf16 g_cnh[S_LEN * KV_LORA],          g_cnl[S_LEN * KV_LORA];
__device__ bf16 g_atth[S_LEN * HID],             g_attl[S_LEN * HID];

// ---------------- helpers --------------------------------------------------
__device__ __forceinline__ uint32_t pk2(bf16 a, bf16 b) {
    return (uint32_t)__bfloat16_as_ushort(a) |
           ((uint32_t)__bfloat16_as_ushort(b) << 16);
}

__device__ __forceinline__ void mma16816(float* c, const uint32_t* a, const uint32_t* b) {
    asm volatile(
        "mma.sync.aligned.m16n8k16.row.col.f32.bf16.bf16.f32 "
        "{%0,%1,%2,%3}, {%4,%5,%6,%7}, {%8,%9}, {%0,%1,%2,%3};\n"
        : "+f"(c[0]), "+f"(c[1]), "+f"(c[2]), "+f"(c[3])
        : "r"(a[0]), "r"(a[1]), "r"(a[2]), "r"(a[3]), "r"(b[0]), "r"(b[1]));
}

// ---------------- fp32 -> (bf16 hi, bf16 lo) split -------------------------
__global__ void split_kernel(const float* __restrict__ x,
                             bf16* __restrict__ h, bf16* __restrict__ l) {
    size_t i = ((size_t)blockIdx.x * 256 + threadIdx.x) * 4;
    float4 v = *(const float4*)&x[i];
    bf16 h0 = __float2bfloat16(v.x), h1 = __float2bfloat16(v.y);
    bf16 h2 = __float2bfloat16(v.z), h3 = __float2bfloat16(v.w);
    bf16 l0 = __float2bfloat16(v.x - __bfloat162float(h0));
    bf16 l1 = __float2bfloat16(v.y - __bfloat162float(h1));
    bf16 l2 = __float2bfloat16(v.z - __bfloat162float(h2));
    bf16 l3 = __float2bfloat16(v.w - __bfloat162float(h3));
    *(uint2*)&h[i] = make_uint2(pk2(h0, h1), pk2(h2, h3));
    *(uint2*)&l[i] = make_uint2(pk2(l0, l1), pk2(l2, l3));
}

// ---------------- bf16x3 GEMM: C[M,N] = (Ah+Al)(Bh+Bl) ---------------------
// 128x128 tile, BK=32, 256 threads (8 warps as 2Mx4N, 64x32 warp tile).
// Double-buffered smem. A smem [m][k] pad 40; B smem [k][n] pad 136.
#define BKP 40
#define BNP 136
#define SMEM_GEMM ((2*128*BKP*2 + 2*32*BNP*2) * 2 * (int)sizeof(bf16) / 2)
// = 2 bufs * (Ah+Al: 128*40 each, Bh+Bl: 32*136 each) * 2B = 75776 bytes
#define SMEM_GEMM_BYTES (2 * (2 * 128 * BKP + 2 * 32 * BNP) * (int)sizeof(bf16))

__global__ void __launch_bounds__(256, 1)
hgemm3_kernel(const bf16* __restrict__ Ah, const bf16* __restrict__ Al,
              const bf16* __restrict__ Bh, const bf16* __restrict__ Bl,
              float* __restrict__ C, int M, int N, int K) {
    extern __shared__ bf16 sm_[];
    bf16* sAh = sm_;                     // [2][128*BKP]
    bf16* sAl = sAh + 2 * 128 * BKP;
    bf16* sBh = sAl + 2 * 128 * BKP;     // [2][32*BNP]
    bf16* sBl = sBh + 2 * 32 * BNP;

    const int tid = threadIdx.x;
    const int lane = tid & 31, wid = tid >> 5;
    const int g = lane >> 2, tg = lane & 3;
    const int warp_m = wid >> 2, warp_n = wid & 3;
    const int row0 = blockIdx.y * 128, col0 = blockIdx.x * 128;

    const int ar0 = tid >> 2, akc = tid & 3;   // A chunk: rows ar0, ar0+64
    const int bk0 = tid >> 4, bnch = tid & 15; // B chunk: k rows bk0, bk0+16
    const int colb = col0 + bnch * 8;
    const bool bv = colb < N;

    float acc[16][4];
#pragma unroll
    for (int i = 0; i < 16; i++)
#pragma unroll
        for (int j = 0; j < 4; j++) acc[i][j] = 0.f;

    uint4 rAh[2], rAl[2], rBh[2], rBl[2];
    const uint4 zz = make_uint4(0, 0, 0, 0);
    const int nt = K / 32;

    // prologue: load tile 0
    {
        size_t a0 = (size_t)(row0 + ar0) * K + akc * 8;
        size_t a1 = (size_t)(row0 + ar0 + 64) * K + akc * 8;
        rAh[0] = *(const uint4*)(Ah + a0); rAh[1] = *(const uint4*)(Ah + a1);
        rAl[0] = *(const uint4*)(Al + a0); rAl[1] = *(const uint4*)(Al + a1);
        size_t b0 = (size_t)bk0 * N + colb;
        size_t b1 = (size_t)(bk0 + 16) * N + colb;
        rBh[0] = bv ? *(const uint4*)(Bh + b0) : zz;
        rBh[1] = bv ? *(const uint4*)(Bh + b1) : zz;
        rBl[0] = bv ? *(const uint4*)(Bl + b0) : zz;
        rBl[1] = bv ? *(const uint4*)(Bl + b1) : zz;
    }
    {
        bf16* dAh = sAh; bf16* dAl = sAl; bf16* dBh = sBh; bf16* dBl = sBl;
        *(uint4*)(dAh + ar0 * BKP + akc * 8) = rAh[0];
        *(uint4*)(dAh + (ar0 + 64) * BKP + akc * 8) = rAh[1];
        *(uint4*)(dAl + ar0 * BKP + akc * 8) = rAl[0];
        *(uint4*)(dAl + (ar0 + 64) * BKP + akc * 8) = rAl[1];
        *(uint4*)(dBh + bk0 * BNP + bnch * 8) = rBh[0];
        *(uint4*)(dBh + (bk0 + 16) * BNP + bnch * 8) = rBh[1];
        *(uint4*)(dBl + bk0 * BNP + bnch * 8) = rBl[0];
        *(uint4*)(dBl + (bk0 + 16) * BNP + bnch * 8) = rBl[1];
    }
    __syncthreads();

    int buf = 0;
    for (int t = 0; t < nt; t++) {
        if (t + 1 < nt) {
            int k0 = (t + 1) * 32;
            size_t a0 = (size_t)(row0 + ar0) * K + k0 + akc * 8;
            size_t a1 = (size_t)(row0 + ar0 + 64) * K + k0 + akc * 8;
            rAh[0] = *(const uint4*)(Ah + a0); rAh[1] = *(const uint4*)(Ah + a1);
            rAl[0] = *(const uint4*)(Al + a0); rAl[1] = *(const uint4*)(Al + a1);
            size_t b0 = (size_t)(k0 + bk0) * N + colb;
            size_t b1 = (size_t)(k0 + bk0 + 16) * N + colb;
            rBh[0] = bv ? *(const uint4*)(Bh + b0) : zz;
            rBh[1] = bv ? *(const uint4*)(Bh + b1) : zz;
            rBl[0] = bv ? *(const uint4*)(Bl + b0) : zz;
            rBl[1] = bv ? *(const uint4*)(Bl + b1) : zz;
        }

        const bf16* cAh = sAh + buf * 128 * BKP;
        const bf16* cAl = sAl + buf * 128 * BKP;
        const bf16* cBh = sBh + buf * 32 * BNP;
        const bf16* cBl = sBl + buf * 32 * BNP;

#pragma unroll
        for (int kk = 0; kk < 2; kk++) {
            uint32_t fAh[4][4], fAl[4][4], fBh[4][2], fBl[4][2];
#pragma unroll
            for (int mf = 0; mf < 4; mf++) {
                const bf16* p = cAh + (warp_m * 64 + mf * 16 + g) * BKP + kk * 16 + tg * 2;
                fAh[mf][0] = *(const uint32_t*)p;
                fAh[mf][1] = *(const uint32_t*)(p + 8 * BKP);
                fAh[mf][2] = *(const uint32_t*)(p + 8);
                fAh[mf][3] = *(const uint32_t*)(p + 8 * BKP + 8);
                const bf16* q = cAl + (warp_m * 64 + mf * 16 + g) * BKP + kk * 16 + tg * 2;
                fAl[mf][0] = *(const uint32_t*)q;
                fAl[mf][1] = *(const uint32_t*)(q + 8 * BKP);
                fAl[mf][2] = *(const uint32_t*)(q + 8);
                fAl[mf][3] = *(const uint32_t*)(q + 8 * BKP + 8);
            }
#pragma unroll
            for (int nf = 0; nf < 4; nf++) {
                const bf16* p = cBh + (kk * 16 + tg * 2) * BNP + warp_n * 32 + nf * 8 + g;
                fBh[nf][0] = pk2(p[0], p[BNP]);
                fBh[nf][1] = pk2(p[8 * BNP], p[9 * BNP]);
                const bf16* q = cBl + (kk * 16 + tg * 2) * BNP + warp_n * 32 + nf * 8 + g;
                fBl[nf][0] = pk2(q[0], q[BNP]);
                fBl[nf][1] = pk2(q[8 * BNP], q[9 * BNP]);
            }
#pragma unroll
            for (int mf = 0; mf < 4; mf++)
#pragma unroll
                for (int nf = 0; nf < 4; nf++) {
                    float* c = acc[mf * 4 + nf];
                    mma16816(c, fAh[mf], fBh[nf]);
                    mma16816(c, fAh[mf], fBl[nf]);
                    mma16816(c, fAl[mf], fBh[nf]);
                }
        }

        if (t + 1 < nt) {
            int nb = buf ^ 1;
            bf16* dAh = sAh + nb * 128 * BKP;
            bf16* dAl = sAl + nb * 128 * BKP;
            bf16* dBh = sBh + nb * 32 * BNP;
            bf16* dBl = sBl + nb * 32 * BNP;
            *(uint4*)(dAh + ar0 * BKP + akc * 8) = rAh[0];
            *(uint4*)(dAh + (ar0 + 64) * BKP + akc * 8) = rAh[1];
            *(uint4*)(dAl + ar0 * BKP + akc * 8) = rAl[0];
            *(uint4*)(dAl + (ar0 + 64) * BKP + akc * 8) = rAl[1];
            *(uint4*)(dBh + bk0 * BNP + bnch * 8) = rBh[0];
            *(uint4*)(dBh + (bk0 + 16) * BNP + bnch * 8) = rBh[1];
            *(uint4*)(dBl + bk0 * BNP + bnch * 8) = rBl[0];
            *(uint4*)(dBl + (bk0 + 16) * BNP + bnch * 8) = rBl[1];
            __syncthreads();
            buf = nb;
        }
    }

#pragma unroll
    for (int mf = 0; mf < 4; mf++)
#pragma unroll
        for (int nf = 0; nf < 4; nf++) {
            int r = row0 + warp_m * 64 + mf * 16 + g;
            int cc = col0 + warp_n * 32 + nf * 8 + tg * 2;
            if (cc < N) {
                float* a = acc[mf * 4 + nf];
                *(float2*)&C[(size_t)r * N + cc] = make_float2(a[0], a[1]);
                *(float2*)&C[(size_t)(r + 8) * N + cc] = make_float2(a[2], a[3]);
            }
        }
}

// ---------------- RMSNorm with fused bf16 split output ---------------------
__global__ void rmsnorm_split_kernel(const float* __restrict__ in,
                                     const float* __restrict__ w,
                                     bf16* __restrict__ oh, bf16* __restrict__ ol,
                                     int width, int instride) {
    int row = blockIdx.x;
    const float* xr = in + (size_t)row * instride;
    float ss = 0.f;
    for (int i = threadIdx.x; i < width; i += 256) {
        float v = xr[i];
        ss += v * v;
    }
    __shared__ float red[256];
    red[threadIdx.x] = ss;
    __syncthreads();
#pragma unroll
    for (int s = 128; s > 0; s >>= 1) {
        if (threadIdx.x < s) red[threadIdx.x] += red[threadIdx.x + s];
        __syncthreads();
    }
    float scale = rsqrtf(red[0] / width + 1e-6f);
    for (int i = threadIdx.x; i < width; i += 256) {
        float v = xr[i] * scale * w[i];
        bf16 hv = __float2bfloat16(v);
        oh[(size_t)row * width + i] = hv;
        ol[(size_t)row * width + i] = __float2bfloat16(v - __bfloat162float(hv));
    }
}

// ---------------- RoPE table (fp64 angles, computed once) ------------------
__global__ void rope_table_kernel(const int* __restrict__ position) {
    int s = blockIdx.x, i = threadIdx.x;
    double pos = (double)position[s];
    double invf = pow(10000.0, -((double)(2 * i)) / 64.0);
    double ang = pos * invf;
    g_rope[s * 64 + i] = (float)cos(ang);
    g_rope[s * 64 + 32 + i] = (float)sin(ang);
}

// ---------------- RoPE + head-major repack ---------------------------------
__global__ void rope_pack_kernel(const float* __restrict__ q,
                                 const float* __restrict__ kv,
                                 const float* __restrict__ c,
                                 float* __restrict__ qs,
                                 float* __restrict__ ks,
                                 float* __restrict__ vs) {
    int s = blockIdx.x, h = blockIdx.y, d = threadIdx.x;
    float qv, kvv;
    if (d < NOPE_D) {
        qv = q[(size_t)s * (NH * Q_HD) + h * Q_HD + d];
        kvv = kv[(size_t)s * (NH * KV_UPD) + h * KV_UPD + d];
        vs[((size_t)h * S_LEN + s) * V_D + d] =
            kv[(size_t)s * (NH * KV_UPD) + h * KV_UPD + NOPE_D + d];
    } else {
        int dr = d - NOPE_D;
        int i = dr & 31;
        float cv = g_rope[s * 64 + i];
        float sv = g_rope[s * 64 + 32 + i];
        const float* qr = q + (size_t)s * (NH * Q_HD) + h * Q_HD + NOPE_D;
        float xq = qr[dr];
        float rq = (dr < 32) ? -qr[dr + 32] : qr[dr - 32];
        qv = xq * cv + rq * sv;
        const float* kr = c + (size_t)s * (KV_LORA + ROPE_D) + KV_LORA;
        float xk = kr[dr];
        float rk = (dr < 32) ? -kr[dr + 32] : kr[dr - 32];
        kvv = xk * cv + rk * sv;
    }
    qs[((size_t)h * S_LEN + s) * Q_HD + d] = qv;
    ks[((size_t)h * S_LEN + s) * Q_HD + d] = kvv;
}

// ---------------- flash attention (causal), fp32, split-bf16 output --------
#define KPAD2 196
#define SPAD 66
#define ATTN_SMEM_FLOATS (64 * Q_HD + 64 * KPAD2 + 64 * V_D + 64 * SPAD + 192)

__global__ void attn_kernel(const float* __restrict__ qs,
                            const float* __restrict__ ks,
                            const float* __restrict__ vs,
                            bf16* __restrict__ att_h,
                            bf16* __restrict__ att_l) {
    extern __shared__ float sm[];
    float* Qs = sm;
    float* Ks = Qs + 64 * Q_HD;
    float* Vs = Ks + 64 * KPAD2;
    float* Ss = Vs + 64 * V_D;
    float* mrow = Ss + 64 * SPAD;
    float* lrow = mrow + 64;
    float* frow = lrow + 64;

    int qt = gridDim.x - 1 - blockIdx.x;
    int h = blockIdx.y;
    int tid = threadIdx.x;
    int ty = tid >> 4, tx = tid & 15;

    const float* qh = qs + (size_t)h * S_LEN * Q_HD;
    const float* kh = ks + (size_t)h * S_LEN * Q_HD;
    const float* vh = vs + (size_t)h * S_LEN * V_D;

#pragma unroll
    for (int idx = tid; idx < 64 * 48; idx += 256) {
        int r = idx / 48, c4 = idx % 48;
        *(float4*)&Qs[r * Q_HD + c4 * 4] =
            *(const float4*)&qh[((size_t)qt * 64 + r) * Q_HD + c4 * 4];
    }
    if (tid < 64) { mrow[tid] = -1e30f; lrow[tid] = 0.f; }

    float o[4][8];
#pragma unroll
    for (int i = 0; i < 4; i++)
#pragma unroll
        for (int j = 0; j < 8; j++) o[i][j] = 0.f;

    const float sc = 0.08838834764831845f;
    int rr = tid >> 2, rq = tid & 3;

    for (int kt = 0; kt <= qt; kt++) {
        __syncthreads();
#pragma unroll
        for (int idx = tid; idx < 64 * 48; idx += 256) {
            int r = idx / 48, c4 = idx % 48;
            *(float4*)&Ks[r * KPAD2 + c4 * 4] =
                *(const float4*)&kh[((size_t)kt * 64 + r) * Q_HD + c4 * 4];
        }
#pragma unroll
        for (int idx = tid; idx < 64 * 32; idx += 256)
            *(float4*)&Vs[idx * 4] = *(const float4*)&vh[(size_t)kt * 64 * V_D + idx * 4];
        __syncthreads();

        float acc[4][4];
#pragma unroll
        for (int i = 0; i < 4; i++)
#pragma unroll
            for (int j = 0; j < 4; j++) acc[i][j] = 0.f;
        for (int k = 0; k < Q_HD; k += 4) {
            float4 a4[4], b4[4];
#pragma unroll
            for (int i = 0; i < 4; i++) a4[i] = *(float4*)&Qs[(ty * 4 + i) * Q_HD + k];
#pragma unroll
            for (int j = 0; j < 4; j++) b4[j] = *(float4*)&Ks[(tx + 16 * j) * KPAD2 + k];
#pragma unroll
            for (int i = 0; i < 4; i++)
#pragma unroll
                for (int j = 0; j < 4; j++) {
                    acc[i][j] += a4[i].x * b4[j].x;
                    acc[i][j] += a4[i].y * b4[j].y;
                    acc[i][j] += a4[i].z * b4[j].z;
                    acc[i][j] += a4[i].w * b4[j].w;
                }
        }
        bool diag = (kt == qt);
#pragma unroll
        for (int i = 0; i < 4; i++)
#pragma unroll
            for (int j = 0; j < 4; j++) {
                int r = ty * 4 + i, cc = tx + 16 * j;
                float v = acc[i][j] * sc;
                if (diag && cc > r) v = -1e30f;
                Ss[r * SPAD + cc] = v;
            }
        __syncthreads();

        {
            float mold = mrow[rr];
            float mt = -1e30f;
#pragma unroll
            for (int c2 = rq * 16; c2 < rq * 16 + 16; c2++)
                mt = fmaxf(mt, Ss[rr * SPAD + c2]);
            mt = fmaxf(mt, __shfl_xor_sync(0xFFFFFFFFu, mt, 1, 4));
            mt = fmaxf(mt, __shfl_xor_sync(0xFFFFFFFFu, mt, 2, 4));
            float nm = fmaxf(mold, mt);
            float sum = 0.f;
#pragma unroll
            for (int c2 = rq * 16; c2 < rq * 16 + 16; c2++) {
                float p = __expf(Ss[rr * SPAD + c2] - nm);
                Ss[rr * SPAD + c2] = p;
                sum += p;
            }
            sum += __shfl_xor_sync(0xFFFFFFFFu, sum, 1, 4);
            sum += __shfl_xor_sync(0xFFFFFFFFu, sum, 2, 4);
            __syncwarp();
            if (rq == 0) {
                float f = __expf(mold - nm);
                lrow[rr] = lrow[rr] * f + sum;
                frow[rr] = f;
                mrow[rr] = nm;
            }
        }
        __syncthreads();

#pragma unroll
        for (int i = 0; i < 4; i++) {
            float f = frow[ty * 4 + i];
#pragma unroll
            for (int j = 0; j < 8; j++) o[i][j] *= f;
        }
        for (int k = 0; k < 64; k++) {
            float p[4];
#pragma unroll
            for (int i = 0; i < 4; i++) p[i] = Ss[(ty * 4 + i) * SPAD + k];
            float4 v0 = *(float4*)&Vs[k * V_D + tx * 4];
            float4 v1 = *(float4*)&Vs[k * V_D + 64 + tx * 4];
#pragma unroll
            for (int i = 0; i < 4; i++) {
                o[i][0] += p[i] * v0.x; o[i][1] += p[i] * v0.y;
                o[i][2] += p[i] * v0.z; o[i][3] += p[i] * v0.w;
                o[i][4] += p[i] * v1.x; o[i][5] += p[i] * v1.y;
                o[i][6] += p[i] * v1.z; o[i][7] += p[i] * v1.w;
            }
        }
    }

#pragma unroll
    for (int i = 0; i < 4; i++) {
        int r = ty * 4 + i;
        float inv = 1.f / lrow[r];
        size_t base = ((size_t)(qt * 64 + r)) * HID + h * V_D;
#pragma unroll
        for (int jj = 0; jj < 2; jj++) {
            float v0 = o[i][jj * 4 + 0] * inv;
            float v1 = o[i][jj * 4 + 1] * inv;
            float v2 = o[i][jj * 4 + 2] * inv;
            float v3 = o[i][jj * 4 + 3] * inv;
            bf16 h0 = __float2bfloat16(v0), h1 = __float2bfloat16(v1);
            bf16 h2 = __float2bfloat16(v2), h3 = __float2bfloat16(v3);
            bf16 l0 = __float2bfloat16(v0 - __bfloat162float(h0));
            bf16 l1 = __float2bfloat16(v1 - __bfloat162float(h1));
            bf16 l2 = __float2bfloat16(v2 - __bfloat162float(h2));
            bf16 l3 = __float2bfloat16(v3 - __bfloat162float(h3));
            *(uint2*)&att_h[base + jj * 64 + tx * 4] = make_uint2(pk2(h0, h1), pk2(h2, h3));
            *(uint2*)&att_l[base + jj * 64 + tx * 4] = make_uint2(pk2(l0, l1), pk2(l2, l3));
        }
    }
}

// ---------------------------------------------------------------------------
extern "C" void kernel_launch(void* const* d_in, const int* in_sizes, int n_in,
                              void* d_out, int out_size) {
    const float* x        = (const float*)d_in[0];
    const int*   position = (const int*)d_in[1];
    // d_in[2] = mask (causal, hardcoded)
    const float* Wq_down  = (const float*)d_in[3];
    const float* q_norm_w = (const float*)d_in[4];
    const float* Wq_up    = (const float*)d_in[5];
    const float* Wkv_down = (const float*)d_in[6];
    const float* kv_norm_w= (const float*)d_in[7];
    const float* Wkv_up   = (const float*)d_in[8];
    const float* Wout     = (const float*)d_in[9];
    float* out = (float*)d_out;

    float *qdown, *q, *c, *kv, *qs, *ks, *vs;
    bf16 *xh, *xl, *wqdh, *wqdl, *wquh, *wqul, *wkdh, *wkdl, *wkuh, *wkul;
    bf16 *woh, *wol, *qnh, *qnl, *cnh, *cnl, *atth, *attl;
    cudaGetSymbolAddress((void**)&qdown, g_qdown);
    cudaGetSymbolAddress((void**)&q, g_q);
    cudaGetSymbolAddress((void**)&c, g_c);
    cudaGetSymbolAddress((void**)&kv, g_kv);
    cudaGetSymbolAddress((void**)&qs, g_qs);
    cudaGetSymbolAddress((void**)&ks, g_ks);
    cudaGetSymbolAddress((void**)&vs, g_vs);
    cudaGetSymbolAddress((void**)&xh, g_xh);   cudaGetSymbolAddress((void**)&xl, g_xl);
    cudaGetSymbolAddress((void**)&wqdh, g_wqdh); cudaGetSymbolAddress((void**)&wqdl, g_wqdl);
    cudaGetSymbolAddress((void**)&wquh, g_wquh); cudaGetSymbolAddress((void**)&wqul, g_wqul);
    cudaGetSymbolAddress((void**)&wkdh, g_wkdh); cudaGetSymbolAddress((void**)&wkdl, g_wkdl);
    cudaGetSymbolAddress((void**)&wkuh, g_wkuh); cudaGetSymbolAddress((void**)&wkul, g_wkul);
    cudaGetSymbolAddress((void**)&woh, g_woh);   cudaGetSymbolAddress((void**)&wol, g_wol);
    cudaGetSymbolAddress((void**)&qnh, g_qnh);   cudaGetSymbolAddress((void**)&qnl, g_qnl);
    cudaGetSymbolAddress((void**)&cnh, g_cnh);   cudaGetSymbolAddress((void**)&cnl, g_cnl);
    cudaGetSymbolAddress((void**)&atth, g_atth); cudaGetSymbolAddress((void**)&attl, g_attl);

    // splits (inputs + weights)
    split_kernel<<<(S_LEN * HID) / 1024, 256>>>(x, xh, xl);
    split_kernel<<<(HID * Q_LORA) / 1024, 256>>>(Wq_down, wqdh, wqdl);
    split_kernel<<<(Q_LORA * NH * Q_HD) / 1024, 256>>>(Wq_up, wquh, wqul);
    split_kernel<<<(HID * (KV_LORA + ROPE_D)) / 1024, 256>>>(Wkv_down, wkdh, wkdl);
    split_kernel<<<(KV_LORA * NH * KV_UPD) / 1024, 256>>>(Wkv_up, wkuh, wkul);
    split_kernel<<<(HID * HID) / 1024, 256>>>(Wout, woh, wol);

    rope_table_kernel<<<S_LEN, 32>>>(position);

    cudaFuncSetAttribute(hgemm3_kernel, cudaFuncAttributeMaxDynamicSharedMemorySize,
                         SMEM_GEMM_BYTES);
    dim3 blk(256);

    // q path
    hgemm3_kernel<<<dim3(Q_LORA / 128, S_LEN / 128), blk, SMEM_GEMM_BYTES>>>(
        xh, xl, wqdh, wqdl, qdown, S_LEN, Q_LORA, HID);
    rmsnorm_split_kernel<<<S_LEN, 256>>>(qdown, q_norm_w, qnh, qnl, Q_LORA, Q_LORA);
    hgemm3_kernel<<<dim3((NH * Q_HD) / 128, S_LEN / 128), blk, SMEM_GEMM_BYTES>>>(
        qnh, qnl, wquh, wqul, q, S_LEN, NH * Q_HD, Q_LORA);

    // kv path (N=576 -> 5 col tiles with guard)
    hgemm3_kernel<<<dim3(5, S_LEN / 128), blk, SMEM_GEMM_BYTES>>>(
        xh, xl, wkdh, wkdl, c, S_LEN, KV_LORA + ROPE_D, HID);
    rmsnorm_split_kernel<<<S_LEN, 256>>>(c, kv_norm_w, cnh, cnl, KV_LORA, KV_LORA + ROPE_D);
    hgemm3_kernel<<<dim3((NH * KV_UPD) / 128, S_LEN / 128), blk, SMEM_GEMM_BYTES>>>(
        cnh, cnl, wkuh, wkul, kv, S_LEN, NH * KV_UPD, KV_LORA);

    // rope + repack
    rope_pack_kernel<<<dim3(S_LEN, NH), Q_HD>>>(q, kv, c, qs, ks, vs);

    // attention (fp32 SIMT, split-bf16 output)
    size_t smem = ATTN_SMEM_FLOATS * sizeof(float);
    cudaFuncSetAttribute(attn_kernel, cudaFuncAttributeMaxDynamicSharedMemorySize, (int)smem);
    attn_kernel<<<dim3(S_LEN / 64, NH), blk, smem>>>(qs, ks, vs, atth, attl);

    // output projection
    hgemm3_kernel<<<dim3(HID / 128, S_LEN / 128), blk, SMEM_GEMM_BYTES>>>(
        atth, attl, woh, wol, out, S_LEN, HID, HID);
}

// round 5
// speedup vs baseline: 2.5619x; 1.0022x over previous
#include <cuda_runtime.h>
#include <cuda_bf16.h>
#include <math.h>
#include <stdint.h>

typedef __nv_bfloat16 bf16;

// ---------------------------------------------------------------------------
// MLA forward. Round 3: GEMMs via bf16x3 split-precision tensor-core mma.sync.
// Shapes: B=1, S=2048, HID=2048, H=16, Q_LORA=1536, KV_LORA=512,
//         ROPE_D=64, NOPE_D=128, V_D=128, Q_HD=192.
// ---------------------------------------------------------------------------

#define S_LEN 2048
#define HID 2048
#define NH 16
#define Q_LORA 1536
#define KV_LORA 512
#define ROPE_D 64
#define NOPE_D 128
#define V_D 128
#define Q_HD 192
#define KV_UPD 256

// ---------------- scratch (static device globals; no allocation) -----------
__device__ float g_qdown[S_LEN * Q_LORA];
__device__ float g_q[S_LEN * NH * Q_HD];
__device__ float g_c[S_LEN * (KV_LORA + ROPE_D)];
__device__ float g_kv[S_LEN * NH * KV_UPD];
__device__ float g_qs[NH * S_LEN * Q_HD];
__device__ float g_ks[NH * S_LEN * Q_HD];
__device__ float g_vs[NH * S_LEN * V_D];
__device__ float g_rope[S_LEN * 64];

// bf16 split pairs
__device__ bf16 g_xh[S_LEN * HID],               g_xl[S_LEN * HID];
__device__ bf16 g_wqdh[HID * Q_LORA],            g_wqdl[HID * Q_LORA];
__device__ bf16 g_wquh[Q_LORA * NH * Q_HD],      g_wqul[Q_LORA * NH * Q_HD];
__device__ bf16 g_wkdh[HID * (KV_LORA + ROPE_D)], g_wkdl[HID * (KV_LORA + ROPE_D)];
__device__ bf16 g_wkuh[KV_LORA * NH * KV_UPD],   g_wkul[KV_LORA * NH * KV_UPD];
__device__ bf16 g_woh[HID * HID],                g_wol[HID * HID];
__device__ bf16 g_qnh[S_LEN * Q_LORA],           g_qnl[S_LEN * Q_LORA];
__device__ bf16 g_cnh[S_LEN * KV_LORA],          g_cnl[S_LEN * KV_LORA];
__device__ bf16 g_atth[S_LEN * HID],             g_attl[S_LEN * HID];

// ---------------- helpers --------------------------------------------------
__device__ __forceinline__ uint32_t pk2(bf16 a, bf16 b) {
    return (uint32_t)__bfloat16_as_ushort(a) |
           ((uint32_t)__bfloat16_as_ushort(b) << 16);
}

__device__ __forceinline__ void mma16816(float* c, const uint32_t* a, const uint32_t* b) {
    asm volatile(
        "mma.sync.aligned.m16n8k16.row.col.f32.bf16.bf16.f32 "
        "{%0,%1,%2,%3}, {%4,%5,%6,%7}, {%8,%9}, {%0,%1,%2,%3};\n"
        : "+f"(c[0]), "+f"(c[1]), "+f"(c[2]), "+f"(c[3])
        : "r"(a[0]), "r"(a[1]), "r"(a[2]), "r"(a[3]), "r"(b[0]), "r"(b[1]));
}

// ---------------- fp32 -> (bf16 hi, bf16 lo) split -------------------------
__global__ void split_kernel(const float* __restrict__ x,
                             bf16* __restrict__ h, bf16* __restrict__ l) {
    size_t i = ((size_t)blockIdx.x * 256 + threadIdx.x) * 4;
    float4 v = *(const float4*)&x[i];
    bf16 h0 = __float2bfloat16(v.x), h1 = __float2bfloat16(v.y);
    bf16 h2 = __float2bfloat16(v.z), h3 = __float2bfloat16(v.w);
    bf16 l0 = __float2bfloat16(v.x - __bfloat162float(h0));
    bf16 l1 = __float2bfloat16(v.y - __bfloat162float(h1));
    bf16 l2 = __float2bfloat16(v.z - __bfloat162float(h2));
    bf16 l3 = __float2bfloat16(v.w - __bfloat162float(h3));
    *(uint2*)&h[i] = make_uint2(pk2(h0, h1), pk2(h2, h3));
    *(uint2*)&l[i] = make_uint2(pk2(l0, l1), pk2(l2, l3));
}

// ---------------- bf16x3 GEMM: C[M,N] = (Ah+Al)(Bh+Bl) ---------------------
// 128x128 tile, BK=32, 256 threads (8 warps as 2Mx4N, 64x32 warp tile).
// Double-buffered smem. A smem [m][k] pad 40; B smem [k][n] pad 136.
#define BKP 40
#define BNP 136
#define SMEM_GEMM ((2*128*BKP*2 + 2*32*BNP*2) * 2 * (int)sizeof(bf16) / 2)
// = 2 bufs * (Ah+Al: 128*40 each, Bh+Bl: 32*136 each) * 2B = 75776 bytes
#define SMEM_GEMM_BYTES (2 * (2 * 128 * BKP + 2 * 32 * BNP) * (int)sizeof(bf16))

__global__ void __launch_bounds__(256, 1)
hgemm3_kernel(const bf16* __restrict__ Ah, const bf16* __restrict__ Al,
              const bf16* __restrict__ Bh, const bf16* __restrict__ Bl,
              float* __restrict__ C, int M, int N, int K) {
    extern __shared__ bf16 sm_[];
    bf16* sAh = sm_;                     // [2][128*BKP]
    bf16* sAl = sAh + 2 * 128 * BKP;
    bf16* sBh = sAl + 2 * 128 * BKP;     // [2][32*BNP]
    bf16* sBl = sBh + 2 * 32 * BNP;

    const int tid = threadIdx.x;
    const int lane = tid & 31, wid = tid >> 5;
    const int g = lane >> 2, tg = lane & 3;
    const int warp_m = wid >> 2, warp_n = wid & 3;
    const int row0 = blockIdx.y * 128, col0 = blockIdx.x * 128;

    const int ar0 = tid >> 2, akc = tid & 3;   // A chunk: rows ar0, ar0+64
    const int bk0 = tid >> 4, bnch = tid & 15; // B chunk: k rows bk0, bk0+16
    const int colb = col0 + bnch * 8;
    const bool bv = colb < N;

    float acc[16][4];
#pragma unroll
    for (int i = 0; i < 16; i++)
#pragma unroll
        for (int j = 0; j < 4; j++) acc[i][j] = 0.f;

    uint4 rAh[2], rAl[2], rBh[2], rBl[2];
    const uint4 zz = make_uint4(0, 0, 0, 0);
    const int nt = K / 32;

    // prologue: load tile 0
    {
        size_t a0 = (size_t)(row0 + ar0) * K + akc * 8;
        size_t a1 = (size_t)(row0 + ar0 + 64) * K + akc * 8;
        rAh[0] = *(const uint4*)(Ah + a0); rAh[1] = *(const uint4*)(Ah + a1);
        rAl[0] = *(const uint4*)(Al + a0); rAl[1] = *(const uint4*)(Al + a1);
        size_t b0 = (size_t)bk0 * N + colb;
        size_t b1 = (size_t)(bk0 + 16) * N + colb;
        rBh[0] = bv ? *(const uint4*)(Bh + b0) : zz;
        rBh[1] = bv ? *(const uint4*)(Bh + b1) : zz;
        rBl[0] = bv ? *(const uint4*)(Bl + b0) : zz;
        rBl[1] = bv ? *(const uint4*)(Bl + b1) : zz;
    }
    {
        bf16* dAh = sAh; bf16* dAl = sAl; bf16* dBh = sBh; bf16* dBl = sBl;
        *(uint4*)(dAh + ar0 * BKP + akc * 8) = rAh[0];
        *(uint4*)(dAh + (ar0 + 64) * BKP + akc * 8) = rAh[1];
        *(uint4*)(dAl + ar0 * BKP + akc * 8) = rAl[0];
        *(uint4*)(dAl + (ar0 + 64) * BKP + akc * 8) = rAl[1];
        *(uint4*)(dBh + bk0 * BNP + bnch * 8) = rBh[0];
        *(uint4*)(dBh + (bk0 + 16) * BNP + bnch * 8) = rBh[1];
        *(uint4*)(dBl + bk0 * BNP + bnch * 8) = rBl[0];
        *(uint4*)(dBl + (bk0 + 16) * BNP + bnch * 8) = rBl[1];
    }
    __syncthreads();

    int buf = 0;
    for (int t = 0; t < nt; t++) {
        if (t + 1 < nt) {
            int k0 = (t + 1) * 32;
            size_t a0 = (size_t)(row0 + ar0) * K + k0 + akc * 8;
            size_t a1 = (size_t)(row0 + ar0 + 64) * K + k0 + akc * 8;
            rAh[0] = *(const uint4*)(Ah + a0); rAh[1] = *(const uint4*)(Ah + a1);
            rAl[0] = *(const uint4*)(Al + a0); rAl[1] = *(const uint4*)(Al + a1);
            size_t b0 = (size_t)(k0 + bk0) * N + colb;
            size_t b1 = (size_t)(k0 + bk0 + 16) * N + colb;
            rBh[0] = bv ? *(const uint4*)(Bh + b0) : zz;
            rBh[1] = bv ? *(const uint4*)(Bh + b1) : zz;
            rBl[0] = bv ? *(const uint4*)(Bl + b0) : zz;
            rBl[1] = bv ? *(const uint4*)(Bl + b1) : zz;
        }

        const bf16* cAh = sAh + buf * 128 * BKP;
        const bf16* cAl = sAl + buf * 128 * BKP;
        const bf16* cBh = sBh + buf * 32 * BNP;
        const bf16* cBl = sBl + buf * 32 * BNP;

#pragma unroll
        for (int kk = 0; kk < 2; kk++) {
            uint32_t fAh[4][4], fAl[4][4], fBh[4][2], fBl[4][2];
#pragma unroll
            for (int mf = 0; mf < 4; mf++) {
                const bf16* p = cAh + (warp_m * 64 + mf * 16 + g) * BKP + kk * 16 + tg * 2;
                fAh[mf][0] = *(const uint32_t*)p;
                fAh[mf][1] = *(const uint32_t*)(p + 8 * BKP);
                fAh[mf][2] = *(const uint32_t*)(p + 8);
                fAh[mf][3] = *(const uint32_t*)(p + 8 * BKP + 8);
                const bf16* q = cAl + (warp_m * 64 + mf * 16 + g) * BKP + kk * 16 + tg * 2;
                fAl[mf][0] = *(const uint32_t*)q;
                fAl[mf][1] = *(const uint32_t*)(q + 8 * BKP);
                fAl[mf][2] = *(const uint32_t*)(q + 8);
                fAl[mf][3] = *(const uint32_t*)(q + 8 * BKP + 8);
            }
#pragma unroll
            for (int nf = 0; nf < 4; nf++) {
                const bf16* p = cBh + (kk * 16 + tg * 2) * BNP + warp_n * 32 + nf * 8 + g;
                fBh[nf][0] = pk2(p[0], p[BNP]);
                fBh[nf][1] = pk2(p[8 * BNP], p[9 * BNP]);
                const bf16* q = cBl + (kk * 16 + tg * 2) * BNP + warp_n * 32 + nf * 8 + g;
                fBl[nf][0] = pk2(q[0], q[BNP]);
                fBl[nf][1] = pk2(q[8 * BNP], q[9 * BNP]);
            }
#pragma unroll
            for (int mf = 0; mf < 4; mf++)
#pragma unroll
                for (int nf = 0; nf < 4; nf++) {
                    float* c = acc[mf * 4 + nf];
                    mma16816(c, fAh[mf], fBh[nf]);
                    mma16816(c, fAh[mf], fBl[nf]);
                    mma16816(c, fAl[mf], fBh[nf]);
                }
        }

        if (t + 1 < nt) {
            int nb = buf ^ 1;
            bf16* dAh = sAh + nb * 128 * BKP;
            bf16* dAl = sAl + nb * 128 * BKP;
            bf16* dBh = sBh + nb * 32 * BNP;
            bf16* dBl = sBl + nb * 32 * BNP;
            *(uint4*)(dAh + ar0 * BKP + akc * 8) = rAh[0];
            *(uint4*)(dAh + (ar0 + 64) * BKP + akc * 8) = rAh[1];
            *(uint4*)(dAl + ar0 * BKP + akc * 8) = rAl[0];
            *(uint4*)(dAl + (ar0 + 64) * BKP + akc * 8) = rAl[1];
            *(uint4*)(dBh + bk0 * BNP + bnch * 8) = rBh[0];
            *(uint4*)(dBh + (bk0 + 16) * BNP + bnch * 8) = rBh[1];
            *(uint4*)(dBl + bk0 * BNP + bnch * 8) = rBl[0];
            *(uint4*)(dBl + (bk0 + 16) * BNP + bnch * 8) = rBl[1];
            __syncthreads();
            buf = nb;
        }
    }

#pragma unroll
    for (int mf = 0; mf < 4; mf++)
#pragma unroll
        for (int nf = 0; nf < 4; nf++) {
            int r = row0 + warp_m * 64 + mf * 16 + g;
            int cc = col0 + warp_n * 32 + nf * 8 + tg * 2;
            if (cc < N) {
                float* a = acc[mf * 4 + nf];
                *(float2*)&C[(size_t)r * N + cc] = make_float2(a[0], a[1]);
                *(float2*)&C[(size_t)(r + 8) * N + cc] = make_float2(a[2], a[3]);
            }
        }
}

// ---------------- RMSNorm with fused bf16 split output ---------------------
__global__ void rmsnorm_split_kernel(const float* __restrict__ in,
                                     const float* __restrict__ w,
                                     bf16* __restrict__ oh, bf16* __restrict__ ol,
                                     int width, int instride) {
    int row = blockIdx.x;
    const float* xr = in + (size_t)row * instride;
    float ss = 0.f;
    for (int i = threadIdx.x; i < width; i += 256) {
        float v = xr[i];
        ss += v * v;
    }
    __shared__ float red[256];
    red[threadIdx.x] = ss;
    __syncthreads();
#pragma unroll
    for (int s = 128; s > 0; s >>= 1) {
        if (threadIdx.x < s) red[threadIdx.x] += red[threadIdx.x + s];
        __syncthreads();
    }
    float scale = rsqrtf(red[0] / width + 1e-6f);
    for (int i = threadIdx.x; i < width; i += 256) {
        float v = xr[i] * scale * w[i];
        bf16 hv = __float2bfloat16(v);
        oh[(size_t)row * width + i] = hv;
        ol[(size_t)row * width + i] = __float2bfloat16(v - __bfloat162float(hv));
    }
}

// ---------------- RoPE table (fp64 angles, computed once) ------------------
__global__ void rope_table_kernel(const int* __restrict__ position) {
    int s = blockIdx.x, i = threadIdx.x;
    double pos = (double)position[s];
    double invf = pow(10000.0, -((double)(2 * i)) / 64.0);
    double ang = pos * invf;
    g_rope[s * 64 + i] = (float)cos(ang);
    g_rope[s * 64 + 32 + i] = (float)sin(ang);
}

// ---------------- RoPE + head-major repack ---------------------------------
__global__ void rope_pack_kernel(const float* __restrict__ q,
                                 const float* __restrict__ kv,
                                 const float* __restrict__ c,
                                 float* __restrict__ qs,
                                 float* __restrict__ ks,
                                 float* __restrict__ vs) {
    int s = blockIdx.x, h = blockIdx.y, d = threadIdx.x;
    float qv, kvv;
    if (d < NOPE_D) {
        qv = q[(size_t)s * (NH * Q_HD) + h * Q_HD + d];
        kvv = kv[(size_t)s * (NH * KV_UPD) + h * KV_UPD + d];
        vs[((size_t)h * S_LEN + s) * V_D + d] =
            kv[(size_t)s * (NH * KV_UPD) + h * KV_UPD + NOPE_D + d];
    } else {
        int dr = d - NOPE_D;
        int i = dr & 31;
        float cv = g_rope[s * 64 + i];
        float sv = g_rope[s * 64 + 32 + i];
        const float* qr = q + (size_t)s * (NH * Q_HD) + h * Q_HD + NOPE_D;
        float xq = qr[dr];
        float rq = (dr < 32) ? -qr[dr + 32] : qr[dr - 32];
        qv = xq * cv + rq * sv;
        const float* kr = c + (size_t)s * (KV_LORA + ROPE_D) + KV_LORA;
        float xk = kr[dr];
        float rk = (dr < 32) ? -kr[dr + 32] : kr[dr - 32];
        kvv = xk * cv + rk * sv;
    }
    qs[((size_t)h * S_LEN + s) * Q_HD + d] = qv;
    ks[((size_t)h * S_LEN + s) * Q_HD + d] = kvv;
}

// ---------------- flash attention (causal), fp32, split-bf16 output --------
#define KPAD2 196
#define SPAD 66
#define ATTN_SMEM_FLOATS (64 * Q_HD + 64 * KPAD2 + 64 * V_D + 64 * SPAD + 192)

__global__ void attn_kernel(const float* __restrict__ qs,
                            const float* __restrict__ ks,
                            const float* __restrict__ vs,
                            bf16* __restrict__ att_h,
                            bf16* __restrict__ att_l) {
    extern __shared__ float sm[];
    float* Qs = sm;
    float* Ks = Qs + 64 * Q_HD;
    float* Vs = Ks + 64 * KPAD2;
    float* Ss = Vs + 64 * V_D;
    float* mrow = Ss + 64 * SPAD;
    float* lrow = mrow + 64;
    float* frow = lrow + 64;

    int qt = gridDim.x - 1 - blockIdx.x;
    int h = blockIdx.y;
    int tid = threadIdx.x;
    int ty = tid >> 4, tx = tid & 15;

    const float* qh = qs + (size_t)h * S_LEN * Q_HD;
    const float* kh = ks + (size_t)h * S_LEN * Q_HD;
    const float* vh = vs + (size_t)h * S_LEN * V_D;

#pragma unroll
    for (int idx = tid; idx < 64 * 48; idx += 256) {
        int r = idx / 48, c4 = idx % 48;
        *(float4*)&Qs[r * Q_HD + c4 * 4] =
            *(const float4*)&qh[((size_t)qt * 64 + r) * Q_HD + c4 * 4];
    }
    if (tid < 64) { mrow[tid] = -1e30f; lrow[tid] = 0.f; }

    float o[4][8];
#pragma unroll
    for (int i = 0; i < 4; i++)
#pragma unroll
        for (int j = 0; j < 8; j++) o[i][j] = 0.f;

    const float sc = 0.08838834764831845f;
    int rr = tid >> 2, rq = tid & 3;

    for (int kt = 0; kt <= qt; kt++) {
        __syncthreads();
#pragma unroll
        for (int idx = tid; idx < 64 * 48; idx += 256) {
            int r = idx / 48, c4 = idx % 48;
            *(float4*)&Ks[r * KPAD2 + c4 * 4] =
                *(const float4*)&kh[((size_t)kt * 64 + r) * Q_HD + c4 * 4];
        }
#pragma unroll
        for (int idx = tid; idx < 64 * 32; idx += 256)
            *(float4*)&Vs[idx * 4] = *(const float4*)&vh[(size_t)kt * 64 * V_D + idx * 4];
        __syncthreads();

        float acc[4][4];
#pragma unroll
        for (int i = 0; i < 4; i++)
#pragma unroll
            for (int j = 0; j < 4; j++) acc[i][j] = 0.f;
        for (int k = 0; k < Q_HD; k += 4) {
            float4 a4[4], b4[4];
#pragma unroll
            for (int i = 0; i < 4; i++) a4[i] = *(float4*)&Qs[(ty * 4 + i) * Q_HD + k];
#pragma unroll
            for (int j = 0; j < 4; j++) b4[j] = *(float4*)&Ks[(tx + 16 * j) * KPAD2 + k];
#pragma unroll
            for (int i = 0; i < 4; i++)
#pragma unroll
                for (int j = 0; j < 4; j++) {
                    acc[i][j] += a4[i].x * b4[j].x;
                    acc[i][j] += a4[i].y * b4[j].y;
                    acc[i][j] += a4[i].z * b4[j].z;
                    acc[i][j] += a4[i].w * b4[j].w;
                }
        }
        bool diag = (kt == qt);
#pragma unroll
        for (int i = 0; i < 4; i++)
#pragma unroll
            for (int j = 0; j < 4; j++) {
                int r = ty * 4 + i, cc = tx + 16 * j;
                float v = acc[i][j] * sc;
                if (diag && cc > r) v = -1e30f;
                Ss[r * SPAD + cc] = v;
            }
        __syncthreads();

        {
            float mold = mrow[rr];
            float mt = -1e30f;
#pragma unroll
            for (int c2 = rq * 16; c2 < rq * 16 + 16; c2++)
                mt = fmaxf(mt, Ss[rr * SPAD + c2]);
            mt = fmaxf(mt, __shfl_xor_sync(0xFFFFFFFFu, mt, 1, 4));
            mt = fmaxf(mt, __shfl_xor_sync(0xFFFFFFFFu, mt, 2, 4));
            float nm = fmaxf(mold, mt);
            float sum = 0.f;
#pragma unroll
            for (int c2 = rq * 16; c2 < rq * 16 + 16; c2++) {
                float p = __expf(Ss[rr * SPAD + c2] - nm);
                Ss[rr * SPAD + c2] = p;
                sum += p;
            }
            sum += __shfl_xor_sync(0xFFFFFFFFu, sum, 1, 4);
            sum += __shfl_xor_sync(0xFFFFFFFFu, sum, 2, 4);
            __syncwarp();
            if (rq == 0) {
                float f = __expf(mold - nm);
                lrow[rr] = lrow[rr] * f + sum;
                frow[rr] = f;
                mrow[rr] = nm;
            }
        }
        __syncthreads();

#pragma unroll
        for (int i = 0; i < 4; i++) {
            float f = frow[ty * 4 + i];
#pragma unroll
            for (int j = 0; j < 8; j++) o[i][j] *= f;
        }
        for (int k = 0; k < 64; k++) {
            float p[4];
#pragma unroll
            for (int i = 0; i < 4; i++) p[i] = Ss[(ty * 4 + i) * SPAD + k];
            float4 v0 = *(float4*)&Vs[k * V_D + tx * 4];
            float4 v1 = *(float4*)&Vs[k * V_D + 64 + tx * 4];
#pragma unroll
            for (int i = 0; i < 4; i++) {
                o[i][0] += p[i] * v0.x; o[i][1] += p[i] * v0.y;
                o[i][2] += p[i] * v0.z; o[i][3] += p[i] * v0.w;
                o[i][4] += p[i] * v1.x; o[i][5] += p[i] * v1.y;
                o[i][6] += p[i] * v1.z; o[i][7] += p[i] * v1.w;
            }
        }
    }

#pragma unroll
    for (int i = 0; i < 4; i++) {
        int r = ty * 4 + i;
        float inv = 1.f / lrow[r];
        size_t base = ((size_t)(qt * 64 + r)) * HID + h * V_D;
#pragma unroll
        for (int jj = 0; jj < 2; jj++) {
            float v0 = o[i][jj * 4 + 0] * inv;
            float v1 = o[i][jj * 4 + 1] * inv;
            float v2 = o[i][jj * 4 + 2] * inv;
            float v3 = o[i][jj * 4 + 3] * inv;
            bf16 h0 = __float2bfloat16(v0), h1 = __float2bfloat16(v1);
            bf16 h2 = __float2bfloat16(v2), h3 = __float2bfloat16(v3);
            bf16 l0 = __float2bfloat16(v0 - __bfloat162float(h0));
            bf16 l1 = __float2bfloat16(v1 - __bfloat162float(h1));
            bf16 l2 = __float2bfloat16(v2 - __bfloat162float(h2));
            bf16 l3 = __float2bfloat16(v3 - __bfloat162float(h3));
            *(uint2*)&att_h[base + jj * 64 + tx * 4] = make_uint2(pk2(h0, h1), pk2(h2, h3));
            *(uint2*)&att_l[base + jj * 64 + tx * 4] = make_uint2(pk2(l0, l1), pk2(l2, l3));
        }
    }
}

// ---------------------------------------------------------------------------
extern "C" void kernel_launch(void* const* d_in, const int* in_sizes, int n_in,
                              void* d_out, int out_size) {
    const float* x        = (const float*)d_in[0];
    const int*   position = (const int*)d_in[1];
    // d_in[2] = mask (causal, hardcoded)
    const float* Wq_down  = (const float*)d_in[3];
    const float* q_norm_w = (const float*)d_in[4];
    const float* Wq_up    = (const float*)d_in[5];
    const float* Wkv_down = (const float*)d_in[6];
    const float* kv_norm_w= (const float*)d_in[7];
    const float* Wkv_up   = (const float*)d_in[8];
    const float* Wout     = (const float*)d_in[9];
    float* out = (float*)d_out;

    float *qdown, *q, *c, *kv, *qs, *ks, *vs;
    bf16 *xh, *xl, *wqdh, *wqdl, *wquh, *wqul, *wkdh, *wkdl, *wkuh, *wkul;
    bf16 *woh, *wol, *qnh, *qnl, *cnh, *cnl, *atth, *attl;
    cudaGetSymbolAddress((void**)&qdown, g_qdown);
    cudaGetSymbolAddress((void**)&q, g_q);
    cudaGetSymbolAddress((void**)&c, g_c);
    cudaGetSymbolAddress((void**)&kv, g_kv);
    cudaGetSymbolAddress((void**)&qs, g_qs);
    cudaGetSymbolAddress((void**)&ks, g_ks);
    cudaGetSymbolAddress((void**)&vs, g_vs);
    cudaGetSymbolAddress((void**)&xh, g_xh);   cudaGetSymbolAddress((void**)&xl, g_xl);
    cudaGetSymbolAddress((void**)&wqdh, g_wqdh); cudaGetSymbolAddress((void**)&wqdl, g_wqdl);
    cudaGetSymbolAddress((void**)&wquh, g_wquh); cudaGetSymbolAddress((void**)&wqul, g_wqul);
    cudaGetSymbolAddress((void**)&wkdh, g_wkdh); cudaGetSymbolAddress((void**)&wkdl, g_wkdl);
    cudaGetSymbolAddress((void**)&wkuh, g_wkuh); cudaGetSymbolAddress((void**)&wkul, g_wkul);
    cudaGetSymbolAddress((void**)&woh, g_woh);   cudaGetSymbolAddress((void**)&wol, g_wol);
    cudaGetSymbolAddress((void**)&qnh, g_qnh);   cudaGetSymbolAddress((void**)&qnl, g_qnl);
    cudaGetSymbolAddress((void**)&cnh, g_cnh);   cudaGetSymbolAddress((void**)&cnl, g_cnl);
    cudaGetSymbolAddress((void**)&atth, g_atth); cudaGetSymbolAddress((void**)&attl, g_attl);

    // splits (inputs + weights)
    split_kernel<<<(S_LEN * HID) / 1024, 256>>>(x, xh, xl);
    split_kernel<<<(HID * Q_LORA) / 1024, 256>>>(Wq_down, wqdh, wqdl);
    split_kernel<<<(Q_LORA * NH * Q_HD) / 1024, 256>>>(Wq_up, wquh, wqul);
    split_kernel<<<(HID * (KV_LORA + ROPE_D)) / 1024, 256>>>(Wkv_down, wkdh, wkdl);
    split_kernel<<<(KV_LORA * NH * KV_UPD) / 1024, 256>>>(Wkv_up, wkuh, wkul);
    split_kernel<<<(HID * HID) / 1024, 256>>>(Wout, woh, wol);

    rope_table_kernel<<<S_LEN, 32>>>(position);

    cudaFuncSetAttribute(hgemm3_kernel, cudaFuncAttributeMaxDynamicSharedMemorySize,
                         SMEM_GEMM_BYTES);
    dim3 blk(256);

    // q path
    hgemm3_kernel<<<dim3(Q_LORA / 128, S_LEN / 128), blk, SMEM_GEMM_BYTES>>>(
        xh, xl, wqdh, wqdl, qdown, S_LEN, Q_LORA, HID);
    rmsnorm_split_kernel<<<S_LEN, 256>>>(qdown, q_norm_w, qnh, qnl, Q_LORA, Q_LORA);
    hgemm3_kernel<<<dim3((NH * Q_HD) / 128, S_LEN / 128), blk, SMEM_GEMM_BYTES>>>(
        qnh, qnl, wquh, wqul, q, S_LEN, NH * Q_HD, Q_LORA);

    // kv path (N=576 -> 5 col tiles with guard)
    hgemm3_kernel<<<dim3(5, S_LEN / 128), blk, SMEM_GEMM_BYTES>>>(
        xh, xl, wkdh, wkdl, c, S_LEN, KV_LORA + ROPE_D, HID);
    rmsnorm_split_kernel<<<S_LEN, 256>>>(c, kv_norm_w, cnh, cnl, KV_LORA, KV_LORA + ROPE_D);
    hgemm3_kernel<<<dim3((NH * KV_UPD) / 128, S_LEN / 128), blk, SMEM_GEMM_BYTES>>>(
        cnh, cnl, wkuh, wkul, kv, S_LEN, NH * KV_UPD, KV_LORA);

    // rope + repack
    rope_pack_kernel<<<dim3(S_LEN, NH), Q_HD>>>(q, kv, c, qs, ks, vs);

    // attention (fp32 SIMT, split-bf16 output)
    size_t smem = ATTN_SMEM_FLOATS * sizeof(float);
    cudaFuncSetAttribute(attn_kernel, cudaFuncAttributeMaxDynamicSharedMemorySize, (int)smem);
    attn_kernel<<<dim3(S_LEN / 64, NH), blk, smem>>>(qs, ks, vs, atth, attl);

    // output projection
    hgemm3_kernel<<<dim3(HID / 128, S_LEN / 128), blk, SMEM_GEMM_BYTES>>>(
        atth, attl, woh, wol, out, S_LEN, HID, HID);
}